// round 7
// baseline (speedup 1.0000x reference)
#include <cuda_runtime.h>
#include <cstdint>

#define NRAYS 16384
#define NFINE 128

typedef unsigned long long u64;

// ---- packed fp32x2 helpers (sm_100+ PTX) ----
__device__ __forceinline__ u64 pack2(float lo, float hi) {
    u64 r; asm("mov.b64 %0, {%1, %2};" : "=l"(r) : "f"(lo), "f"(hi)); return r;
}
__device__ __forceinline__ void unpack2(u64 v, float& lo, float& hi) {
    asm("mov.b64 {%0, %1}, %2;" : "=f"(lo), "=f"(hi) : "l"(v));
}
__device__ __forceinline__ void fma2(u64& d, u64 a, u64 b) {
    asm("fma.rn.f32x2 %0, %1, %2, %0;" : "+l"(d) : "l"(a), "l"(b));
}

// ---- fast transcendentals (MUFU-based; rel err ~2^-21 << 1e-3 tol) ----
__device__ __forceinline__ float fexp(float x)   { return __expf(x); }
__device__ __forceinline__ float fexp10(float x) { return __exp10f(x); }
__device__ __forceinline__ float frsqrt_approx(float x) {
    float r; asm("rsqrt.approx.f32 %0, %1;" : "=f"(r) : "f"(x)); return r;
}
__device__ __forceinline__ float fsigmoid(float x) {
    return __fdividef(1.0f, 1.0f + __expf(-x));
}
__device__ __forceinline__ float fsoftplus(float x) {
    return fmaxf(x, 0.0f) + __logf(1.0f + __expf(-fabsf(x)));
}

// exact z-grid helpers
__device__ __forceinline__ float zlog_c(int i) {
    return (i < 128) ? (float)(i - 128) * 0.0078125f : (float)(i - 128) * 0.015625f;
}
__device__ __forceinline__ float zmid_c(int i) {
    return 0.5f * (zlog_c(i) + zlog_c(i + 1));
}

__device__ __forceinline__ unsigned rotl32(unsigned x, int r) {
    return __funnelshift_l(x, x, r);
}

// JAX threefry2x32, key=(0,42), partitionable counter mode: bits = out0^out1
__device__ __forceinline__ float tf_uniform(unsigned idx) {
    unsigned x0 = 0u, x1 = idx;
    const unsigned ks1 = 42u;
    const unsigned ks2 = 42u ^ 0x1BD11BDAu;
    x0 += 0u; x1 += ks1;
#define TF_RND(R) { x0 += x1; x1 = rotl32(x1, R); x1 ^= x0; }
    TF_RND(13) TF_RND(15) TF_RND(26) TF_RND(6)
    x0 += ks1; x1 += ks2 + 1u;
    TF_RND(17) TF_RND(29) TF_RND(16) TF_RND(24)
    x0 += ks2; x1 += 0u + 2u;
    TF_RND(13) TF_RND(15) TF_RND(26) TF_RND(6)
    x0 += 0u; x1 += ks1 + 3u;
    TF_RND(17) TF_RND(29) TF_RND(16) TF_RND(24)
    x0 += ks1; x1 += ks2 + 4u;
    TF_RND(13) TF_RND(15) TF_RND(26) TF_RND(6)
    x0 += ks2; x1 += 0u + 5u;
#undef TF_RND
    unsigned bits = x0 ^ x1;
    return __uint_as_float((bits >> 9) | 0x3f800000u) - 1.0f;
}

// mip scale via rsqrt trick: r = rsqrt(d2) == 1/d;  d = d2*r;  s = (2-r)*r
__device__ __forceinline__ void mip_scale(float& x, float& y, float& z) {
    float d2 = x * x + y * y + z * z;
    float r  = frsqrt_approx(d2);
    float d  = d2 * r;
    if (d > 1.0f) {
        float s = (2.0f - r) * r;
        x *= s; y *= s; z *= s;
    }
}

__global__ void __launch_bounds__(128, 4) nerf_fused(
    const float* __restrict__ gh, const float* __restrict__ gw,
    const float* __restrict__ gK, const float* __restrict__ gE,
    const float* __restrict__ gbg,
    const float* __restrict__ gWd1, const float* __restrict__ gbd1,
    const float* __restrict__ gWd2, const float* __restrict__ gbd2,
    const float* __restrict__ gWc1, const float* __restrict__ gbc1,
    const float* __restrict__ gWc2, const float* __restrict__ gbc2,
    float* __restrict__ oImg, float* __restrict__ oW,
    float* __restrict__ oZ, float* __restrict__ oInv)
{
    __shared__ float4 sWd1p[32];                      // (w0,w1,w2,b) per hidden c
    __shared__ float  sWd2[32];
    __shared__ __align__(16) float sWc1[1120];        // [35][32] row-major
    __shared__ __align__(16) float sBc1[32];
    __shared__ __align__(16) float sWc2c[3][32];      // column-major Wc2
    __shared__ float sCdf[4][256];                    // cdf + +inf padding

    const int tid = threadIdx.x;
    for (int i = tid; i < 1120; i += 128) sWc1[i] = gWc1[i];
    if (tid < 32) {
        sWd1p[tid] = make_float4(gWd1[tid], gWd1[32 + tid], gWd1[64 + tid], gbd1[tid]);
        sWd2[tid]  = gWd2[tid];
        sBc1[tid]  = gbc1[tid];
        sWc2c[0][tid] = gWc2[tid * 3 + 0];
        sWc2c[1][tid] = gWc2[tid * 3 + 1];
        sWc2c[2][tid] = gWc2[tid * 3 + 2];
    }
    __syncthreads();

    const int lane = tid & 31;
    const int warp = tid >> 5;
    const int ray  = (blockIdx.x << 2) + warp;

    // ---- ray setup ----
    float k00 = gK[0], k01 = gK[1], k02 = gK[2];
    float k10 = gK[3], k11 = gK[4], k12 = gK[5];
    float k20 = gK[6], k21 = gK[7], k22 = gK[8];
    float det = k00 * (k11 * k22 - k12 * k21)
              + k01 * (k12 * k20 - k10 * k22)
              + k02 * (k10 * k21 - k11 * k20);
    float id = 1.0f / det;
    float i00 = (k11 * k22 - k12 * k21) * id, i01 = (k02 * k21 - k01 * k22) * id, i02 = (k01 * k12 - k02 * k11) * id;
    float i10 = (k12 * k20 - k10 * k22) * id, i11 = (k00 * k22 - k02 * k20) * id, i12 = (k02 * k10 - k00 * k12) * id;
    float i20 = (k10 * k21 - k11 * k20) * id, i21 = (k01 * k20 - k00 * k21) * id, i22 = (k00 * k11 - k01 * k10) * id;

    float dvx = gw[ray] + 0.5f, dvy = gh[ray] + 0.5f;
    float cx = dvx * i00 + dvy * i01 + i02;
    float cy = dvx * i10 + dvy * i11 + i12;
    float cz = dvx * i20 + dvy * i21 + i22;

    const float* Er = gE + (size_t)ray * 16;
    float ox = Er[3], oy = Er[7], oz = Er[11];
    float rdx = Er[0] * cx + Er[1] * cy + Er[2]  * cz;
    float rdy = Er[4] * cx + Er[5] * cy + Er[6]  * cz;
    float rdz = Er[8] * cx + Er[9] * cy + Er[10] * cz;
    float rn  = sqrtf(rdx * rdx + rdy * rdy + rdz * rdz);
    float irn = __fdividef(1.0f, rn);
    float ndx = rdx * irn, ndy = rdy * irn, ndz = rdz * irn;

    const float bd2v = gbd2[0];

    // ---- coarse pass: 6 samples/lane, density MLP only ----
    float alpha[6];
#pragma unroll
    for (int p = 0; p < 3; ++p) {
        const int s0 = lane * 6 + 2 * p;
        float zl0 = zlog_c(s0), zl1 = zlog_c(s0 + 1);
        float z0 = fexp10(zl0), z1 = fexp10(zl1);
        float px0 = fmaf(rdx, z0, ox), py0 = fmaf(rdy, z0, oy), pz0 = fmaf(rdz, z0, oz);
        float px1 = fmaf(rdx, z1, ox), py1 = fmaf(rdy, z1, oy), pz1 = fmaf(rdz, z1, oz);
        mip_scale(px0, py0, pz0);
        mip_scale(px1, py1, pz1);
        float sg0 = bd2v, sg1 = bd2v;
#pragma unroll 4
        for (int c = 0; c < 32; ++c) {
            float4 wd = sWd1p[c];
            float v2 = sWd2[c];
            float t0 = fmaf(px0, wd.x, fmaf(py0, wd.y, fmaf(pz0, wd.z, wd.w)));
            float t1 = fmaf(px1, wd.x, fmaf(py1, wd.y, fmaf(pz1, wd.z, wd.w)));
            t0 = fmaxf(t0, 0.0f); t1 = fmaxf(t1, 0.0f);
            sg0 = fmaf(t0, v2, sg0); sg1 = fmaf(t1, v2, sg1);
        }
        float si0 = fsoftplus(sg0), si1 = fsoftplus(sg1);
        float d0 = (s0     < 128) ? 0.0078125f : ((s0     < 191) ? 0.015625f : 0.0f);
        float d1 = (s0 + 1 < 128) ? 0.0078125f : ((s0 + 1 < 191) ? 0.015625f : 0.0f);
        alpha[2 * p]     = 1.0f - fexp(-si0 * d0);
        alpha[2 * p + 1] = 1.0f - fexp(-si1 * d1);
    }

    // ---- transmittance weights (warp multiplicative scan) ----
    float om[6]; float lprod = 1.0f;
#pragma unroll
    for (int q = 0; q < 6; ++q) { om[q] = 1.0f - alpha[q]; lprod *= om[q]; }
    float scanp = lprod;
#pragma unroll
    for (int o = 1; o < 32; o <<= 1) {
        float t = __shfl_up_sync(0xffffffffu, scanp, o);
        if (lane >= o) scanp *= t;
    }
    float T = __shfl_up_sync(0xffffffffu, scanp, 1);
    if (lane == 0) T = 1.0f;
    float wgt[6];
#pragma unroll
    for (int q = 0; q < 6; ++q) { wgt[q] = alpha[q] * T; T *= om[q]; }

    // ---- reweight ----
    float wprev = __shfl_up_sync(0xffffffffu, wgt[5], 1);   if (lane == 0)  wprev = 0.0f;
    float wnext = __shfl_down_sync(0xffffffffu, wgt[0], 1); if (lane == 31) wnext = 0.0f;
    float wr[6]; float lsum = 0.0f;
#pragma unroll
    for (int q = 0; q < 6; ++q) {
        float wm = (q == 0) ? wprev : wgt[q - 1];
        float wp = (q == 5) ? wnext : wgt[q + 1];
        float v = 0.5f * (fmaxf(wm, wgt[q]) + fmaxf(wgt[q], wp)) + (float)(0.02 / 192.0);
        int s = lane * 6 + q;
        v *= (s < 128) ? (float)(128.0 / 192.0) : (float)(64.0 / 192.0);
        wr[q] = v; lsum += v;
    }
    float tot = lsum;
#pragma unroll
    for (int o = 16; o; o >>= 1) tot += __shfl_xor_sync(0xffffffffu, tot, o);
    float itot = __fdividef(1.0f, tot);

    float wn[6]; float ls2 = 0.0f;
#pragma unroll
    for (int q = 0; q < 6; ++q) { wn[q] = wr[q] * itot; ls2 += wn[q]; }
    float scs = ls2;
#pragma unroll
    for (int o = 1; o < 32; o <<= 1) {
        float t = __shfl_up_sync(0xffffffffu, scs, o);
        if (lane >= o) scs += t;
    }
    float base = __shfl_up_sync(0xffffffffu, scs, 1);
    if (lane == 0) base = 0.0f;
    float run = base;
#pragma unroll
    for (int q = 0; q < 6; ++q) { run += wn[q]; sCdf[warp][lane * 6 + q] = run; }
    sCdf[warp][192 + lane] = 1e30f;
    sCdf[warp][224 + lane] = 1e30f;
    __syncwarp();

    const float cdfl = sCdf[warp][1];
    const float cdfh = sCdf[warp][190];

    // ---- importance sampling: unconditional branchless bit-ladder ----
    float zlf[4];
#pragma unroll
    for (int q = 0; q < 4; ++q) {
        int j = (lane << 2) + q;
        float r = tf_uniform((unsigned)(ray * NFINE + j));
        float u = (float)j * 0.0078125f + r * 0.0078125f;
        u = u * (cdfh - cdfl) + cdfl;
        int k = 0;
#pragma unroll
        for (int s = 128; s >= 1; s >>= 1) {
            int cand = k + s;
            if (cand <= 191 && sCdf[warp][cand] <= u) k = cand;
        }
        float cb = sCdf[warp][k], ca = sCdf[warp][k + 1];
        float tt = __fdividef(u - cb, ca - cb);
        float zb = zmid_c(k), za = zmid_c(k + 1);
        zlf[q] = zb + (za - zb) * tt;
    }

    // ---- fine pass: 4-sample blocking, ONE pass over weights per j-half ----
    float px[4], py[4], pz[4];
#pragma unroll
    for (int q = 0; q < 4; ++q) {
        float zq = fexp10(zlf[q]);
        px[q] = fmaf(rdx, zq, ox);
        py[q] = fmaf(rdy, zq, oy);
        pz[q] = fmaf(rdz, zq, oz);
        mip_scale(px[q], py[q], pz[q]);
    }

    float sg[4]  = { bd2v, bd2v, bd2v, bd2v };
    float ar[4], ag[4], ab[4];
#pragma unroll
    for (int q = 0; q < 4; ++q) { ar[q] = gbc2[0]; ag[q] = gbc2[1]; ab[q] = gbc2[2]; }

#pragma unroll
    for (int hh = 0; hh < 2; ++hh) {
        const int jb = hh << 4;                       // j base: 0 or 16
        u64 acc[4][8];                                // [sample][j-pair] 64 regs
        {
            u64 ndxp = pack2(ndx, ndx), ndyp = pack2(ndy, ndy), ndzp = pack2(ndz, ndz);
            const ulonglong2* b2  = (const ulonglong2*)&sBc1[jb];
            const ulonglong2* wx2 = (const ulonglong2*)&sWc1[1024 + jb];
            const ulonglong2* wy2 = (const ulonglong2*)&sWc1[1056 + jb];
            const ulonglong2* wz2 = (const ulonglong2*)&sWc1[1088 + jb];
#pragma unroll
            for (int g = 0; g < 4; ++g) {
                ulonglong2 b  = b2[g];
                ulonglong2 wx = wx2[g];
                ulonglong2 wy = wy2[g];
                ulonglong2 wz = wz2[g];
                u64 va = b.x, vb = b.y;
                fma2(va, ndxp, wx.x); fma2(vb, ndxp, wx.y);
                fma2(va, ndyp, wy.x); fma2(vb, ndyp, wy.y);
                fma2(va, ndzp, wz.x); fma2(vb, ndzp, wz.y);
#pragma unroll
                for (int q = 0; q < 4; ++q) {
                    acc[q][2 * g] = va;
                    acc[q][2 * g + 1] = vb;
                }
            }
        }

#pragma unroll 2
        for (int c = 0; c < 32; ++c) {
            float4 wd = sWd1p[c];
            u64 tp[4];
#pragma unroll
            for (int q = 0; q < 4; ++q) {
                float t = fmaf(px[q], wd.x, fmaf(py[q], wd.y, fmaf(pz[q], wd.z, wd.w)));
                t = fmaxf(t, 0.0f);
                if (hh == 0) sg[q] = fmaf(t, sWd2[c], sg[q]);
                tp[q] = pack2(t, t);
            }
            const ulonglong2* wc = (const ulonglong2*)&sWc1[c * 32 + jb];
#pragma unroll
            for (int g = 0; g < 4; ++g) {
                ulonglong2 wv = wc[g];
#pragma unroll
                for (int q = 0; q < 4; ++q) {
                    fma2(acc[q][2 * g],     tp[q], wv.x);
                    fma2(acc[q][2 * g + 1], tp[q], wv.y);
                }
            }
        }

        // layer2 partial for this half
#pragma unroll
        for (int g = 0; g < 4; ++g) {
            int j4 = jb + 4 * g;
            float4 u0 = *(const float4*)&sWc2c[0][j4];
            float4 u1 = *(const float4*)&sWc2c[1][j4];
            float4 u2 = *(const float4*)&sWc2c[2][j4];
#pragma unroll
            for (int q = 0; q < 4; ++q) {
                float h0, h1, h2, h3;
                unpack2(acc[q][2 * g],     h0, h1);
                unpack2(acc[q][2 * g + 1], h2, h3);
                h0 = fmaxf(h0, 0.0f); h1 = fmaxf(h1, 0.0f);
                h2 = fmaxf(h2, 0.0f); h3 = fmaxf(h3, 0.0f);
                ar[q] = fmaf(h0, u0.x, ar[q]); ag[q] = fmaf(h0, u1.x, ag[q]); ab[q] = fmaf(h0, u2.x, ab[q]);
                ar[q] = fmaf(h1, u0.y, ar[q]); ag[q] = fmaf(h1, u1.y, ag[q]); ab[q] = fmaf(h1, u2.y, ab[q]);
                ar[q] = fmaf(h2, u0.z, ar[q]); ag[q] = fmaf(h2, u1.z, ag[q]); ab[q] = fmaf(h2, u2.z, ab[q]);
                ar[q] = fmaf(h3, u0.w, ar[q]); ag[q] = fmaf(h3, u1.w, ag[q]); ab[q] = fmaf(h3, u2.w, ab[q]);
            }
        }
    }

    float sig[4], rr[4], rg[4], rb[4];
#pragma unroll
    for (int q = 0; q < 4; ++q) {
        sig[q] = fsoftplus(sg[q]);
        rr[q] = fsigmoid(ar[q]);
        rg[q] = fsigmoid(ag[q]);
        rb[q] = fsigmoid(ab[q]);
    }

    // ---- fine weights + accumulation ----
    float znx = __shfl_down_sync(0xffffffffu, zlf[0], 1);
    float dl[4];
    dl[0] = zlf[1] - zlf[0];
    dl[1] = zlf[2] - zlf[1];
    dl[2] = zlf[3] - zlf[2];
    dl[3] = (lane == 31) ? 0.0f : (znx - zlf[3]);

    float al[4], om2[4]; float lp = 1.0f;
#pragma unroll
    for (int q = 0; q < 4; ++q) {
        al[q] = 1.0f - fexp(-sig[q] * dl[q]);
        om2[q] = 1.0f - al[q];
        lp *= om2[q];
    }
    float scan2 = lp;
#pragma unroll
    for (int o = 1; o < 32; o <<= 1) {
        float t = __shfl_up_sync(0xffffffffu, scan2, o);
        if (lane >= o) scan2 *= t;
    }
    float T2 = __shfl_up_sync(0xffffffffu, scan2, 1);
    if (lane == 0) T2 = 1.0f;
    float w4[4];
#pragma unroll
    for (int q = 0; q < 4; ++q) { w4[q] = al[q] * T2; T2 *= om2[q]; }

    float ir = 0.0f, ig = 0.0f, ib = 0.0f, ivd = 0.0f, ws = 0.0f;
#pragma unroll
    for (int q = 0; q < 4; ++q) {
        ir = fmaf(w4[q], rr[q], ir);
        ig = fmaf(w4[q], rg[q], ig);
        ib = fmaf(w4[q], rb[q], ib);
        ivd = fmaf(w4[q], fexp10(-zlf[q]), ivd);
        ws  += w4[q];
    }
#pragma unroll
    for (int o = 16; o; o >>= 1) {
        ir  += __shfl_xor_sync(0xffffffffu, ir, o);
        ig  += __shfl_xor_sync(0xffffffffu, ig, o);
        ib  += __shfl_xor_sync(0xffffffffu, ib, o);
        ivd += __shfl_xor_sync(0xffffffffu, ivd, o);
        ws  += __shfl_xor_sync(0xffffffffu, ws, o);
    }

    // ---- stores ----
    *(float4*)(oW + (size_t)ray * NFINE + lane * 4) =
        make_float4(w4[0], w4[1], w4[2], w4[3]);
    *(float4*)(oZ + (size_t)ray * NFINE + lane * 4) =
        make_float4((zlf[0] + 1.0f) * 0.5f, (zlf[1] + 1.0f) * 0.5f,
                    (zlf[2] + 1.0f) * 0.5f, (zlf[3] + 1.0f) * 0.5f);

    if (lane == 0) {
        float oneMw = 1.0f - ws;
        oImg[ray * 3 + 0] = ir + oneMw * gbg[0];
        oImg[ray * 3 + 1] = ig + oneMw * gbg[1];
        oImg[ray * 3 + 2] = ib + oneMw * gbg[2];
        oInv[ray] = ivd;
    }
}

extern "C" void kernel_launch(void* const* d_in, const int* in_sizes, int n_in,
                              void* d_out, int out_size) {
    const float* h   = (const float*)d_in[1];
    const float* w   = (const float*)d_in[2];
    const float* K   = (const float*)d_in[3];
    const float* E   = (const float*)d_in[4];
    const float* bg  = (const float*)d_in[5];
    const float* Wd1 = (const float*)d_in[6];
    const float* bd1 = (const float*)d_in[7];
    const float* Wd2 = (const float*)d_in[8];
    const float* bd2 = (const float*)d_in[9];
    const float* Wc1 = (const float*)d_in[10];
    const float* bc1 = (const float*)d_in[11];
    const float* Wc2 = (const float*)d_in[12];
    const float* bc2 = (const float*)d_in[13];

    float* out   = (float*)d_out;
    float* oImg  = out;
    float* oW    = out + NRAYS * 3;
    float* oZ    = oW + (size_t)NRAYS * NFINE;
    float* oInv  = oZ + (size_t)NRAYS * NFINE;

    nerf_fused<<<NRAYS / 4, 128>>>(h, w, K, E, bg,
                                   Wd1, bd1, Wd2, bd2,
                                   Wc1, bc1, Wc2, bc2,
                                   oImg, oW, oZ, oInv);
}

// round 8
// speedup vs baseline: 1.5438x; 1.5438x over previous
#include <cuda_runtime.h>
#include <cstdint>

#define NRAYS 16384
#define NFINE 128

typedef unsigned long long u64;

// ---- packed fp32x2 helpers (sm_100+ PTX) ----
__device__ __forceinline__ u64 pack2(float lo, float hi) {
    u64 r; asm("mov.b64 %0, {%1, %2};" : "=l"(r) : "f"(lo), "f"(hi)); return r;
}
__device__ __forceinline__ void unpack2(u64 v, float& lo, float& hi) {
    asm("mov.b64 {%0, %1}, %2;" : "=f"(lo), "=f"(hi) : "l"(v));
}
__device__ __forceinline__ void fma2(u64& d, u64 a, u64 b) {
    asm("fma.rn.f32x2 %0, %1, %2, %0;" : "+l"(d) : "l"(a), "l"(b));
}

// ---- fast transcendentals (MUFU-based; rel err ~2^-21 << 1e-3 tol) ----
__device__ __forceinline__ float fexp(float x)   { return __expf(x); }
__device__ __forceinline__ float fexp10(float x) { return __exp10f(x); }
__device__ __forceinline__ float frsqrt_approx(float x) {
    float r; asm("rsqrt.approx.f32 %0, %1;" : "=f"(r) : "f"(x)); return r;
}
__device__ __forceinline__ float fsigmoid(float x) {
    return __fdividef(1.0f, 1.0f + __expf(-x));
}
__device__ __forceinline__ float fsoftplus(float x) {
    return fmaxf(x, 0.0f) + __logf(1.0f + __expf(-fabsf(x)));
}

// exact z-grid helpers
__device__ __forceinline__ float zlog_c(int i) {
    return (i < 128) ? (float)(i - 128) * 0.0078125f : (float)(i - 128) * 0.015625f;
}
__device__ __forceinline__ float zmid_c(int i) {
    return 0.5f * (zlog_c(i) + zlog_c(i + 1));
}

__device__ __forceinline__ unsigned rotl32(unsigned x, int r) {
    return __funnelshift_l(x, x, r);
}

// JAX threefry2x32, key=(0,42), partitionable counter mode: bits = out0^out1
__device__ __forceinline__ float tf_uniform(unsigned idx) {
    unsigned x0 = 0u, x1 = idx;
    const unsigned ks1 = 42u;
    const unsigned ks2 = 42u ^ 0x1BD11BDAu;
    x0 += 0u; x1 += ks1;
#define TF_RND(R) { x0 += x1; x1 = rotl32(x1, R); x1 ^= x0; }
    TF_RND(13) TF_RND(15) TF_RND(26) TF_RND(6)
    x0 += ks1; x1 += ks2 + 1u;
    TF_RND(17) TF_RND(29) TF_RND(16) TF_RND(24)
    x0 += ks2; x1 += 0u + 2u;
    TF_RND(13) TF_RND(15) TF_RND(26) TF_RND(6)
    x0 += 0u; x1 += ks1 + 3u;
    TF_RND(17) TF_RND(29) TF_RND(16) TF_RND(24)
    x0 += ks1; x1 += ks2 + 4u;
    TF_RND(13) TF_RND(15) TF_RND(26) TF_RND(6)
    x0 += ks2; x1 += 0u + 5u;
#undef TF_RND
    unsigned bits = x0 ^ x1;
    return __uint_as_float((bits >> 9) | 0x3f800000u) - 1.0f;
}

// mip scale via rsqrt trick: r = rsqrt(d2) == 1/d;  d = d2*r;  s = (2-r)*r
__device__ __forceinline__ void mip_scale(float& x, float& y, float& z) {
    float d2 = x * x + y * y + z * z;
    float r  = frsqrt_approx(d2);
    float d  = d2 * r;
    if (d > 1.0f) {
        float s = (2.0f - r) * r;
        x *= s; y *= s; z *= s;
    }
}

__global__ void __launch_bounds__(128, 4) nerf_fused(
    const float* __restrict__ gh, const float* __restrict__ gw,
    const float* __restrict__ gK, const float* __restrict__ gE,
    const float* __restrict__ gbg,
    const float* __restrict__ gWd1, const float* __restrict__ gbd1,
    const float* __restrict__ gWd2, const float* __restrict__ gbd2,
    const float* __restrict__ gWc1, const float* __restrict__ gbc1,
    const float* __restrict__ gWc2, const float* __restrict__ gbc2,
    float* __restrict__ oImg, float* __restrict__ oW,
    float* __restrict__ oZ, float* __restrict__ oInv)
{
    __shared__ float4 sWd1p[32];                      // (w0,w1,w2,b) per hidden c
    __shared__ float  sWd2[32];
    __shared__ __align__(16) float sWc1[1120];        // [35][32] row-major
    __shared__ __align__(16) float sBc1[32];
    __shared__ __align__(16) float sWc2c[3][32];      // column-major Wc2
    __shared__ float sCdf[4][256];                    // cdf + +inf padding

    const int tid = threadIdx.x;
    for (int i = tid; i < 1120; i += 128) sWc1[i] = gWc1[i];
    if (tid < 32) {
        sWd1p[tid] = make_float4(gWd1[tid], gWd1[32 + tid], gWd1[64 + tid], gbd1[tid]);
        sWd2[tid]  = gWd2[tid];
        sBc1[tid]  = gbc1[tid];
        sWc2c[0][tid] = gWc2[tid * 3 + 0];
        sWc2c[1][tid] = gWc2[tid * 3 + 1];
        sWc2c[2][tid] = gWc2[tid * 3 + 2];
    }
    __syncthreads();

    const int lane = tid & 31;
    const int warp = tid >> 5;
    const int ray  = (blockIdx.x << 2) + warp;

    // ---- ray setup ----
    float k00 = gK[0], k01 = gK[1], k02 = gK[2];
    float k10 = gK[3], k11 = gK[4], k12 = gK[5];
    float k20 = gK[6], k21 = gK[7], k22 = gK[8];
    float det = k00 * (k11 * k22 - k12 * k21)
              + k01 * (k12 * k20 - k10 * k22)
              + k02 * (k10 * k21 - k11 * k20);
    float id = 1.0f / det;
    float i00 = (k11 * k22 - k12 * k21) * id, i01 = (k02 * k21 - k01 * k22) * id, i02 = (k01 * k12 - k02 * k11) * id;
    float i10 = (k12 * k20 - k10 * k22) * id, i11 = (k00 * k22 - k02 * k20) * id, i12 = (k02 * k10 - k00 * k12) * id;
    float i20 = (k10 * k21 - k11 * k20) * id, i21 = (k01 * k20 - k00 * k21) * id, i22 = (k00 * k11 - k01 * k10) * id;

    float dvx = gw[ray] + 0.5f, dvy = gh[ray] + 0.5f;
    float cx = dvx * i00 + dvy * i01 + i02;
    float cy = dvx * i10 + dvy * i11 + i12;
    float cz = dvx * i20 + dvy * i21 + i22;

    const float* Er = gE + (size_t)ray * 16;
    float ox = Er[3], oy = Er[7], oz = Er[11];
    float rdx = Er[0] * cx + Er[1] * cy + Er[2]  * cz;
    float rdy = Er[4] * cx + Er[5] * cy + Er[6]  * cz;
    float rdz = Er[8] * cx + Er[9] * cy + Er[10] * cz;
    float rn  = sqrtf(rdx * rdx + rdy * rdy + rdz * rdz);
    float irn = __fdividef(1.0f, rn);
    float ndx = rdx * irn, ndy = rdy * irn, ndz = rdz * irn;

    const float bd2v = gbd2[0];

    // ---- coarse pass: 6 samples/lane, SINGLE pass over density weights ----
    float alpha[6];
    {
        float cpx[6], cpy[6], cpz[6];
#pragma unroll
        for (int q = 0; q < 6; ++q) {
            float zq = fexp10(zlog_c(lane * 6 + q));
            cpx[q] = fmaf(rdx, zq, ox);
            cpy[q] = fmaf(rdy, zq, oy);
            cpz[q] = fmaf(rdz, zq, oz);
            mip_scale(cpx[q], cpy[q], cpz[q]);
        }
        float sg[6] = { bd2v, bd2v, bd2v, bd2v, bd2v, bd2v };
#pragma unroll 4
        for (int c = 0; c < 32; ++c) {
            float4 wd = sWd1p[c];
            float v2 = sWd2[c];
#pragma unroll
            for (int q = 0; q < 6; ++q) {
                float t = fmaf(cpx[q], wd.x, fmaf(cpy[q], wd.y, fmaf(cpz[q], wd.z, wd.w)));
                t = fmaxf(t, 0.0f);
                sg[q] = fmaf(t, v2, sg[q]);
            }
        }
#pragma unroll
        for (int q = 0; q < 6; ++q) {
            int s = lane * 6 + q;
            float d = (s < 128) ? 0.0078125f : ((s < 191) ? 0.015625f : 0.0f);
            alpha[q] = 1.0f - fexp(-fsoftplus(sg[q]) * d);
        }
    }

    // ---- transmittance weights (warp multiplicative scan) ----
    float om[6]; float lprod = 1.0f;
#pragma unroll
    for (int q = 0; q < 6; ++q) { om[q] = 1.0f - alpha[q]; lprod *= om[q]; }
    float scanp = lprod;
#pragma unroll
    for (int o = 1; o < 32; o <<= 1) {
        float t = __shfl_up_sync(0xffffffffu, scanp, o);
        if (lane >= o) scanp *= t;
    }
    float T = __shfl_up_sync(0xffffffffu, scanp, 1);
    if (lane == 0) T = 1.0f;
    float wgt[6];
#pragma unroll
    for (int q = 0; q < 6; ++q) { wgt[q] = alpha[q] * T; T *= om[q]; }

    // ---- reweight ----
    float wprev = __shfl_up_sync(0xffffffffu, wgt[5], 1);   if (lane == 0)  wprev = 0.0f;
    float wnext = __shfl_down_sync(0xffffffffu, wgt[0], 1); if (lane == 31) wnext = 0.0f;
    float wr[6]; float lsum = 0.0f;
#pragma unroll
    for (int q = 0; q < 6; ++q) {
        float wm = (q == 0) ? wprev : wgt[q - 1];
        float wp = (q == 5) ? wnext : wgt[q + 1];
        float v = 0.5f * (fmaxf(wm, wgt[q]) + fmaxf(wgt[q], wp)) + (float)(0.02 / 192.0);
        int s = lane * 6 + q;
        v *= (s < 128) ? (float)(128.0 / 192.0) : (float)(64.0 / 192.0);
        wr[q] = v; lsum += v;
    }
    float tot = lsum;
#pragma unroll
    for (int o = 16; o; o >>= 1) tot += __shfl_xor_sync(0xffffffffu, tot, o);
    float itot = __fdividef(1.0f, tot);

    float wn[6]; float ls2 = 0.0f;
#pragma unroll
    for (int q = 0; q < 6; ++q) { wn[q] = wr[q] * itot; ls2 += wn[q]; }
    float scs = ls2;
#pragma unroll
    for (int o = 1; o < 32; o <<= 1) {
        float t = __shfl_up_sync(0xffffffffu, scs, o);
        if (lane >= o) scs += t;
    }
    float base = __shfl_up_sync(0xffffffffu, scs, 1);
    if (lane == 0) base = 0.0f;
    float run = base;
#pragma unroll
    for (int q = 0; q < 6; ++q) { run += wn[q]; sCdf[warp][lane * 6 + q] = run; }
    sCdf[warp][192 + lane] = 1e30f;
    sCdf[warp][224 + lane] = 1e30f;
    __syncwarp();

    const float cdfl = sCdf[warp][1];
    const float cdfh = sCdf[warp][190];

    // ---- importance sampling: unconditional branchless bit-ladder ----
    float zlf[4];
#pragma unroll
    for (int q = 0; q < 4; ++q) {
        int j = (lane << 2) + q;
        float r = tf_uniform((unsigned)(ray * NFINE + j));
        float u = (float)j * 0.0078125f + r * 0.0078125f;
        u = u * (cdfh - cdfl) + cdfl;
        int k = 0;
#pragma unroll
        for (int s = 128; s >= 1; s >>= 1) {
            int cand = k + s;
            if (cand <= 191 && sCdf[warp][cand] <= u) k = cand;
        }
        float cb = sCdf[warp][k], ca = sCdf[warp][k + 1];
        float tt = __fdividef(u - cb, ca - cb);
        float zb = zmid_c(k), za = zmid_c(k + 1);
        zlf[q] = zb + (za - zb) * tt;
    }

    // ---- fine pass: streamed features, f32x2 over j-pairs, 2 j-halves ----
    float sig[4], rr[4], rg[4], rb[4];
#pragma unroll
    for (int p = 0; p < 2; ++p) {
        const int q0 = 2 * p, q1 = 2 * p + 1;
        float z0 = fexp10(zlf[q0]), z1 = fexp10(zlf[q1]);
        float px0 = fmaf(rdx, z0, ox), py0 = fmaf(rdy, z0, oy), pz0 = fmaf(rdz, z0, oz);
        float px1 = fmaf(rdx, z1, ox), py1 = fmaf(rdy, z1, oy), pz1 = fmaf(rdz, z1, oz);
        mip_scale(px0, py0, pz0);
        mip_scale(px1, py1, pz1);

        float a0r = gbc2[0], a0g = gbc2[1], a0b = gbc2[2];
        float a1r = a0r, a1g = a0g, a1b = a0b;
        float sg0 = bd2v, sg1 = bd2v;

#pragma unroll
        for (int hh = 0; hh < 2; ++hh) {
            const int jb = hh << 4;                       // j base: 0 or 16
            u64 acc0p[8], acc1p[8];
            {
                u64 ndxp = pack2(ndx, ndx), ndyp = pack2(ndy, ndy), ndzp = pack2(ndz, ndz);
                const ulonglong2* b2  = (const ulonglong2*)&sBc1[jb];
                const ulonglong2* wx2 = (const ulonglong2*)&sWc1[1024 + jb];
                const ulonglong2* wy2 = (const ulonglong2*)&sWc1[1056 + jb];
                const ulonglong2* wz2 = (const ulonglong2*)&sWc1[1088 + jb];
#pragma unroll
                for (int g = 0; g < 4; ++g) {
                    ulonglong2 b  = b2[g];
                    ulonglong2 wx = wx2[g];
                    ulonglong2 wy = wy2[g];
                    ulonglong2 wz = wz2[g];
                    u64 va = b.x, vb = b.y;
                    fma2(va, ndxp, wx.x); fma2(vb, ndxp, wx.y);
                    fma2(va, ndyp, wy.x); fma2(vb, ndyp, wy.y);
                    fma2(va, ndzp, wz.x); fma2(vb, ndzp, wz.y);
                    acc0p[2 * g] = va; acc1p[2 * g] = va;
                    acc0p[2 * g + 1] = vb; acc1p[2 * g + 1] = vb;
                }
            }

#pragma unroll 4
            for (int c = 0; c < 32; ++c) {
                float4 wd = sWd1p[c];
                float t0 = fmaf(px0, wd.x, fmaf(py0, wd.y, fmaf(pz0, wd.z, wd.w)));
                float t1 = fmaf(px1, wd.x, fmaf(py1, wd.y, fmaf(pz1, wd.z, wd.w)));
                t0 = fmaxf(t0, 0.0f); t1 = fmaxf(t1, 0.0f);
                if (hh == 0) {
                    float v2 = sWd2[c];
                    sg0 = fmaf(t0, v2, sg0); sg1 = fmaf(t1, v2, sg1);
                }
                u64 t00 = pack2(t0, t0);
                u64 t11 = pack2(t1, t1);
                const ulonglong2* wc = (const ulonglong2*)&sWc1[c * 32 + jb];
#pragma unroll
                for (int g = 0; g < 4; ++g) {
                    ulonglong2 wv = wc[g];
                    fma2(acc0p[2 * g],     t00, wv.x);
                    fma2(acc0p[2 * g + 1], t00, wv.y);
                    fma2(acc1p[2 * g],     t11, wv.x);
                    fma2(acc1p[2 * g + 1], t11, wv.y);
                }
            }

            // layer2 partial for this half
#pragma unroll
            for (int g = 0; g < 4; ++g) {
                int j4 = jb + 4 * g;
                float4 u0 = *(const float4*)&sWc2c[0][j4];
                float4 u1 = *(const float4*)&sWc2c[1][j4];
                float4 u2 = *(const float4*)&sWc2c[2][j4];
                float h00, h01, h02, h03, h10, h11, h12, h13;
                unpack2(acc0p[2 * g],     h00, h01);
                unpack2(acc0p[2 * g + 1], h02, h03);
                unpack2(acc1p[2 * g],     h10, h11);
                unpack2(acc1p[2 * g + 1], h12, h13);
                h00 = fmaxf(h00, 0.0f); h01 = fmaxf(h01, 0.0f);
                h02 = fmaxf(h02, 0.0f); h03 = fmaxf(h03, 0.0f);
                h10 = fmaxf(h10, 0.0f); h11 = fmaxf(h11, 0.0f);
                h12 = fmaxf(h12, 0.0f); h13 = fmaxf(h13, 0.0f);
                a0r = fmaf(h00, u0.x, a0r); a0g = fmaf(h00, u1.x, a0g); a0b = fmaf(h00, u2.x, a0b);
                a1r = fmaf(h10, u0.x, a1r); a1g = fmaf(h10, u1.x, a1g); a1b = fmaf(h10, u2.x, a1b);
                a0r = fmaf(h01, u0.y, a0r); a0g = fmaf(h01, u1.y, a0g); a0b = fmaf(h01, u2.y, a0b);
                a1r = fmaf(h11, u0.y, a1r); a1g = fmaf(h11, u1.y, a1g); a1b = fmaf(h11, u2.y, a1b);
                a0r = fmaf(h02, u0.z, a0r); a0g = fmaf(h02, u1.z, a0g); a0b = fmaf(h02, u2.z, a0b);
                a1r = fmaf(h12, u0.z, a1r); a1g = fmaf(h12, u1.z, a1g); a1b = fmaf(h12, u2.z, a1b);
                a0r = fmaf(h03, u0.w, a0r); a0g = fmaf(h03, u1.w, a0g); a0b = fmaf(h03, u2.w, a0b);
                a1r = fmaf(h13, u0.w, a1r); a1g = fmaf(h13, u1.w, a1g); a1b = fmaf(h13, u2.w, a1b);
            }
        }

        sig[q0] = fsoftplus(sg0);
        sig[q1] = fsoftplus(sg1);
        rr[q0] = fsigmoid(a0r); rg[q0] = fsigmoid(a0g); rb[q0] = fsigmoid(a0b);
        rr[q1] = fsigmoid(a1r); rg[q1] = fsigmoid(a1g); rb[q1] = fsigmoid(a1b);
    }

    // ---- fine weights + accumulation ----
    float znx = __shfl_down_sync(0xffffffffu, zlf[0], 1);
    float dl[4];
    dl[0] = zlf[1] - zlf[0];
    dl[1] = zlf[2] - zlf[1];
    dl[2] = zlf[3] - zlf[2];
    dl[3] = (lane == 31) ? 0.0f : (znx - zlf[3]);

    float al[4], om2[4]; float lp = 1.0f;
#pragma unroll
    for (int q = 0; q < 4; ++q) {
        al[q] = 1.0f - fexp(-sig[q] * dl[q]);
        om2[q] = 1.0f - al[q];
        lp *= om2[q];
    }
    float scan2 = lp;
#pragma unroll
    for (int o = 1; o < 32; o <<= 1) {
        float t = __shfl_up_sync(0xffffffffu, scan2, o);
        if (lane >= o) scan2 *= t;
    }
    float T2 = __shfl_up_sync(0xffffffffu, scan2, 1);
    if (lane == 0) T2 = 1.0f;
    float w4[4];
#pragma unroll
    for (int q = 0; q < 4; ++q) { w4[q] = al[q] * T2; T2 *= om2[q]; }

    float ir = 0.0f, ig = 0.0f, ib = 0.0f, ivd = 0.0f, ws = 0.0f;
#pragma unroll
    for (int q = 0; q < 4; ++q) {
        ir = fmaf(w4[q], rr[q], ir);
        ig = fmaf(w4[q], rg[q], ig);
        ib = fmaf(w4[q], rb[q], ib);
        ivd = fmaf(w4[q], fexp10(-zlf[q]), ivd);
        ws  += w4[q];
    }
#pragma unroll
    for (int o = 16; o; o >>= 1) {
        ir  += __shfl_xor_sync(0xffffffffu, ir, o);
        ig  += __shfl_xor_sync(0xffffffffu, ig, o);
        ib  += __shfl_xor_sync(0xffffffffu, ib, o);
        ivd += __shfl_xor_sync(0xffffffffu, ivd, o);
        ws  += __shfl_xor_sync(0xffffffffu, ws, o);
    }

    // ---- stores ----
    *(float4*)(oW + (size_t)ray * NFINE + lane * 4) =
        make_float4(w4[0], w4[1], w4[2], w4[3]);
    *(float4*)(oZ + (size_t)ray * NFINE + lane * 4) =
        make_float4((zlf[0] + 1.0f) * 0.5f, (zlf[1] + 1.0f) * 0.5f,
                    (zlf[2] + 1.0f) * 0.5f, (zlf[3] + 1.0f) * 0.5f);

    if (lane == 0) {
        float oneMw = 1.0f - ws;
        oImg[ray * 3 + 0] = ir + oneMw * gbg[0];
        oImg[ray * 3 + 1] = ig + oneMw * gbg[1];
        oImg[ray * 3 + 2] = ib + oneMw * gbg[2];
        oInv[ray] = ivd;
    }
}

extern "C" void kernel_launch(void* const* d_in, const int* in_sizes, int n_in,
                              void* d_out, int out_size) {
    const float* h   = (const float*)d_in[1];
    const float* w   = (const float*)d_in[2];
    const float* K   = (const float*)d_in[3];
    const float* E   = (const float*)d_in[4];
    const float* bg  = (const float*)d_in[5];
    const float* Wd1 = (const float*)d_in[6];
    const float* bd1 = (const float*)d_in[7];
    const float* Wd2 = (const float*)d_in[8];
    const float* bd2 = (const float*)d_in[9];
    const float* Wc1 = (const float*)d_in[10];
    const float* bc1 = (const float*)d_in[11];
    const float* Wc2 = (const float*)d_in[12];
    const float* bc2 = (const float*)d_in[13];

    float* out   = (float*)d_out;
    float* oImg  = out;
    float* oW    = out + NRAYS * 3;
    float* oZ    = oW + (size_t)NRAYS * NFINE;
    float* oInv  = oZ + (size_t)NRAYS * NFINE;

    nerf_fused<<<NRAYS / 4, 128>>>(h, w, K, E, bg,
                                   Wd1, bd1, Wd2, bd2,
                                   Wc1, bc1, Wc2, bc2,
                                   oImg, oW, oZ, oInv);
}

// round 10
// speedup vs baseline: 1.8144x; 1.1753x over previous
#include <cuda_runtime.h>
#include <cstdint>

#define NRAYS 16384
#define NFINE 128

typedef unsigned long long u64;

// ---- fast transcendentals ----
__device__ __forceinline__ float fexp(float x)   { return __expf(x); }
__device__ __forceinline__ float fexp10(float x) { return __exp10f(x); }
__device__ __forceinline__ float frsqrt_approx(float x) {
    float r; asm("rsqrt.approx.f32 %0, %1;" : "=f"(r) : "f"(x)); return r;
}
__device__ __forceinline__ float fsigmoid(float x) {
    return __fdividef(1.0f, 1.0f + __expf(-x));
}
__device__ __forceinline__ float fsoftplus(float x) {
    return fmaxf(x, 0.0f) + __logf(1.0f + __expf(-fabsf(x)));
}
__device__ __forceinline__ uint32_t f2tf32(float x) {
    uint32_t r; asm("cvt.rna.tf32.f32 %0, %1;" : "=r"(r) : "f"(x)); return r;
}
// m16n8k8 tf32 HMMA (standard PTX, sm_80+; runs on sm_103 tensor pipe)
__device__ __forceinline__ void mma_tf32(float* d,
    uint32_t a0, uint32_t a1, uint32_t a2, uint32_t a3,
    uint32_t b0, uint32_t b1)
{
    asm volatile(
        "mma.sync.aligned.m16n8k8.row.col.f32.tf32.tf32.f32 "
        "{%0,%1,%2,%3}, {%4,%5,%6,%7}, {%8,%9}, {%0,%1,%2,%3};"
        : "+f"(d[0]), "+f"(d[1]), "+f"(d[2]), "+f"(d[3])
        : "r"(a0), "r"(a1), "r"(a2), "r"(a3), "r"(b0), "r"(b1));
}

// exact z-grid helpers
__device__ __forceinline__ float zlog_c(int i) {
    return (i < 128) ? (float)(i - 128) * 0.0078125f : (float)(i - 128) * 0.015625f;
}
__device__ __forceinline__ float zmid_c(int i) {
    return 0.5f * (zlog_c(i) + zlog_c(i + 1));
}
__device__ __forceinline__ unsigned rotl32(unsigned x, int r) {
    return __funnelshift_l(x, x, r);
}

// JAX threefry2x32, key=(0,42), partitionable counter mode: bits = out0^out1
__device__ __forceinline__ float tf_uniform(unsigned idx) {
    unsigned x0 = 0u, x1 = idx;
    const unsigned ks1 = 42u;
    const unsigned ks2 = 42u ^ 0x1BD11BDAu;
    x0 += 0u; x1 += ks1;
#define TF_RND(R) { x0 += x1; x1 = rotl32(x1, R); x1 ^= x0; }
    TF_RND(13) TF_RND(15) TF_RND(26) TF_RND(6)
    x0 += ks1; x1 += ks2 + 1u;
    TF_RND(17) TF_RND(29) TF_RND(16) TF_RND(24)
    x0 += ks2; x1 += 0u + 2u;
    TF_RND(13) TF_RND(15) TF_RND(26) TF_RND(6)
    x0 += 0u; x1 += ks1 + 3u;
    TF_RND(17) TF_RND(29) TF_RND(16) TF_RND(24)
    x0 += ks1; x1 += ks2 + 4u;
    TF_RND(13) TF_RND(15) TF_RND(26) TF_RND(6)
    x0 += ks2; x1 += 0u + 5u;
#undef TF_RND
    unsigned bits = x0 ^ x1;
    return __uint_as_float((bits >> 9) | 0x3f800000u) - 1.0f;
}

__device__ __forceinline__ void mip_scale(float& x, float& y, float& z) {
    float d2 = x * x + y * y + z * z;
    float r  = frsqrt_approx(d2);
    float d  = d2 * r;
    if (d > 1.0f) {
        float s = (2.0f - r) * r;
        x *= s; y *= s; z *= s;
    }
}

__global__ void __launch_bounds__(128, 4) nerf_fused(
    const float* __restrict__ gh, const float* __restrict__ gw,
    const float* __restrict__ gK, const float* __restrict__ gE,
    const float* __restrict__ gbg,
    const float* __restrict__ gWd1, const float* __restrict__ gbd1,
    const float* __restrict__ gWd2, const float* __restrict__ gbd2,
    const float* __restrict__ gWc1, const float* __restrict__ gbc1,
    const float* __restrict__ gWc2, const float* __restrict__ gbc2,
    float* __restrict__ oImg, float* __restrict__ oW,
    float* __restrict__ oZ, float* __restrict__ oInv)
{
    __shared__ float4 sWd1p[32];            // (w0,w1,w2,b) per hidden c
    __shared__ float  sWd2[32];
    __shared__ __align__(16) float sWc2c[3][32];
    __shared__ float  sInit[4][32];         // per-ray bc1 + dir terms
    __shared__ uint2  sBfrag[4][4][32];     // b-frags [kt][nt][lane] = (b0,b1) tf32
    __shared__ float  sCdf[4][256];
    __shared__ __align__(16) float sT[4][1024];  // per-warp T tile (32 rows x 32 c) tf32
    __shared__ __align__(16) float sH[4][1024];  // per-warp H tile (D result)

    const int tid  = threadIdx.x;
    const int lane = tid & 31;
    const int warp = tid >> 5;
    const int gid  = lane >> 2;
    const int tig  = lane & 3;
    const int ray  = (blockIdx.x << 2) + warp;

    // ---- stage weights + B fragments ----
    if (tid < 32) {
        sWd1p[tid] = make_float4(gWd1[tid], gWd1[32 + tid], gWd1[64 + tid], gbd1[tid]);
        sWd2[tid]  = gWd2[tid];
        sWc2c[0][tid] = gWc2[tid * 3 + 0];
        sWc2c[1][tid] = gWc2[tid * 3 + 1];
        sWc2c[2][tid] = gWc2[tid * 3 + 2];
    }
    for (int i = tid; i < 512; i += 128) {
        int kt = i >> 7, nt = (i >> 5) & 3, l = i & 31;
        int lt = l & 3, lg = l >> 2;
        int c0 = 8 * kt + lt, j = 8 * nt + lg;
        sBfrag[kt][nt][l] = make_uint2(f2tf32(gWc1[c0 * 32 + j]),
                                       f2tf32(gWc1[(c0 + 4) * 32 + j]));
    }
    __syncthreads();

    // ---- ray setup ----
    float k00 = gK[0], k01 = gK[1], k02 = gK[2];
    float k10 = gK[3], k11 = gK[4], k12 = gK[5];
    float k20 = gK[6], k21 = gK[7], k22 = gK[8];
    float det = k00 * (k11 * k22 - k12 * k21)
              + k01 * (k12 * k20 - k10 * k22)
              + k02 * (k10 * k21 - k11 * k20);
    float id = 1.0f / det;
    float i00 = (k11 * k22 - k12 * k21) * id, i01 = (k02 * k21 - k01 * k22) * id, i02 = (k01 * k12 - k02 * k11) * id;
    float i10 = (k12 * k20 - k10 * k22) * id, i11 = (k00 * k22 - k02 * k20) * id, i12 = (k02 * k10 - k00 * k12) * id;
    float i20 = (k10 * k21 - k11 * k20) * id, i21 = (k01 * k20 - k00 * k21) * id, i22 = (k00 * k11 - k01 * k10) * id;

    float dvx = gw[ray] + 0.5f, dvy = gh[ray] + 0.5f;
    float cx = dvx * i00 + dvy * i01 + i02;
    float cy = dvx * i10 + dvy * i11 + i12;
    float cz = dvx * i20 + dvy * i21 + i22;

    const float* Er = gE + (size_t)ray * 16;
    float ox = Er[3], oy = Er[7], oz = Er[11];
    float rdx = Er[0] * cx + Er[1] * cy + Er[2]  * cz;
    float rdy = Er[4] * cx + Er[5] * cy + Er[6]  * cz;
    float rdz = Er[8] * cx + Er[9] * cy + Er[10] * cz;
    float rn  = sqrtf(rdx * rdx + rdy * rdy + rdz * rdz);
    float irn = __fdividef(1.0f, rn);
    float ndx = rdx * irn, ndy = rdy * irn, ndz = rdz * irn;

    const float bd2v = gbd2[0];

    // per-ray layer1 init: bc1[j] + dir terms (rows 32..34 of Wc1); lane j
    {
        int j = lane;
        float ini = gbc1[j];
        ini = fmaf(ndx, gWc1[1024 + j], ini);
        ini = fmaf(ndy, gWc1[1056 + j], ini);
        ini = fmaf(ndz, gWc1[1088 + j], ini);
        sInit[warp][j] = ini;
    }
    __syncwarp();

    // ---- coarse pass: 6 samples/lane, single pass over density weights ----
    float alpha[6];
    {
        float cpx[6], cpy[6], cpz[6];
#pragma unroll
        for (int q = 0; q < 6; ++q) {
            float zq = fexp10(zlog_c(lane * 6 + q));
            cpx[q] = fmaf(rdx, zq, ox);
            cpy[q] = fmaf(rdy, zq, oy);
            cpz[q] = fmaf(rdz, zq, oz);
            mip_scale(cpx[q], cpy[q], cpz[q]);
        }
        float sg[6] = { bd2v, bd2v, bd2v, bd2v, bd2v, bd2v };
#pragma unroll 4
        for (int c = 0; c < 32; ++c) {
            float4 wd = sWd1p[c];
            float v2 = sWd2[c];
#pragma unroll
            for (int q = 0; q < 6; ++q) {
                float t = fmaf(cpx[q], wd.x, fmaf(cpy[q], wd.y, fmaf(cpz[q], wd.z, wd.w)));
                t = fmaxf(t, 0.0f);
                sg[q] = fmaf(t, v2, sg[q]);
            }
        }
#pragma unroll
        for (int q = 0; q < 6; ++q) {
            int s = lane * 6 + q;
            float d = (s < 128) ? 0.0078125f : ((s < 191) ? 0.015625f : 0.0f);
            alpha[q] = 1.0f - fexp(-fsoftplus(sg[q]) * d);
        }
    }

    // ---- transmittance weights (warp multiplicative scan) ----
    float om[6]; float lprod = 1.0f;
#pragma unroll
    for (int q = 0; q < 6; ++q) { om[q] = 1.0f - alpha[q]; lprod *= om[q]; }
    float scanp = lprod;
#pragma unroll
    for (int o = 1; o < 32; o <<= 1) {
        float t = __shfl_up_sync(0xffffffffu, scanp, o);
        if (lane >= o) scanp *= t;
    }
    float T = __shfl_up_sync(0xffffffffu, scanp, 1);
    if (lane == 0) T = 1.0f;
    float wgt[6];
#pragma unroll
    for (int q = 0; q < 6; ++q) { wgt[q] = alpha[q] * T; T *= om[q]; }

    // ---- reweight ----
    float wprev = __shfl_up_sync(0xffffffffu, wgt[5], 1);   if (lane == 0)  wprev = 0.0f;
    float wnext = __shfl_down_sync(0xffffffffu, wgt[0], 1); if (lane == 31) wnext = 0.0f;
    float wr[6]; float lsum = 0.0f;
#pragma unroll
    for (int q = 0; q < 6; ++q) {
        float wm = (q == 0) ? wprev : wgt[q - 1];
        float wp = (q == 5) ? wnext : wgt[q + 1];
        float v = 0.5f * (fmaxf(wm, wgt[q]) + fmaxf(wgt[q], wp)) + (float)(0.02 / 192.0);
        int s = lane * 6 + q;
        v *= (s < 128) ? (float)(128.0 / 192.0) : (float)(64.0 / 192.0);
        wr[q] = v; lsum += v;
    }
    float tot = lsum;
#pragma unroll
    for (int o = 16; o; o >>= 1) tot += __shfl_xor_sync(0xffffffffu, tot, o);
    float itot = __fdividef(1.0f, tot);

    float wn[6]; float ls2 = 0.0f;
#pragma unroll
    for (int q = 0; q < 6; ++q) { wn[q] = wr[q] * itot; ls2 += wn[q]; }
    float scs = ls2;
#pragma unroll
    for (int o = 1; o < 32; o <<= 1) {
        float t = __shfl_up_sync(0xffffffffu, scs, o);
        if (lane >= o) scs += t;
    }
    float base = __shfl_up_sync(0xffffffffu, scs, 1);
    if (lane == 0) base = 0.0f;
    float run = base;
#pragma unroll
    for (int q = 0; q < 6; ++q) { run += wn[q]; sCdf[warp][lane * 6 + q] = run; }
    sCdf[warp][192 + lane] = 1e30f;
    sCdf[warp][224 + lane] = 1e30f;
    __syncwarp();

    const float cdfl = sCdf[warp][1];
    const float cdfh = sCdf[warp][190];

    // ---- importance sampling: unconditional branchless bit-ladder ----
    float zlf[4];
#pragma unroll
    for (int q = 0; q < 4; ++q) {
        int j = (lane << 2) + q;
        float r = tf_uniform((unsigned)(ray * NFINE + j));
        float u = (float)j * 0.0078125f + r * 0.0078125f;
        u = u * (cdfh - cdfl) + cdfl;
        int k = 0;
#pragma unroll
        for (int s = 128; s >= 1; s >>= 1) {
            int cand = k + s;
            if (sCdf[warp][cand] <= u) k = cand;
        }
        float cb = sCdf[warp][k], ca = sCdf[warp][k + 1];
        float tt = __fdividef(u - cb, ca - cb);
        float zb = zmid_c(k), za = zmid_c(k + 1);
        zlf[q] = zb + (za - zb) * tt;
    }

    // ---- fine pass: per q-tile (samples s = 4*lane + q), HMMA GEMM ----
    const float bc2x = gbc2[0], bc2y = gbc2[1], bc2z = gbc2[2];
    float* aT = sT[warp];
    float* hT = sH[warp];
    float sig[4], rr[4], rg[4], rb[4];

#pragma unroll
    for (int q = 0; q < 4; ++q) {
        // 1) compute hidden t for own sample; stage tf32 T tile; sigma path fp32
        float zq = fexp10(zlf[q]);
        float pxq = fmaf(rdx, zq, ox), pyq = fmaf(rdy, zq, oy), pzq = fmaf(rdz, zq, oz);
        mip_scale(pxq, pyq, pzq);
        float sgq = bd2v;
#pragma unroll
        for (int cg = 0; cg < 8; ++cg) {
            uint4 tc;
#pragma unroll
            for (int cc = 0; cc < 4; ++cc) {
                int c = 4 * cg + cc;
                float4 wd = sWd1p[c];
                float t = fmaf(pxq, wd.x, fmaf(pyq, wd.y, fmaf(pzq, wd.z, wd.w)));
                t = fmaxf(t, 0.0f);
                sgq = fmaf(t, sWd2[c], sgq);
                ((uint32_t*)&tc)[cc] = f2tf32(t);
            }
            *(uint4*)(aT + lane * 32 + 4 * (cg ^ (lane & 7))) = tc;
        }
        sig[q] = fsoftplus(sgq);
        __syncwarp();

        // 2) GEMM: H[32x32] = T[32x32] @ Wc1h, init = sInit  (2 m-tiles of 16)
#pragma unroll
        for (int mt = 0; mt < 2; ++mt) {
            float d[16];
#pragma unroll
            for (int nt = 0; nt < 4; ++nt) {
                int j0 = 8 * nt + 2 * tig;
                float i0 = sInit[warp][j0], i1 = sInit[warp][j0 + 1];
                d[4 * nt + 0] = i0; d[4 * nt + 1] = i1;
                d[4 * nt + 2] = i0; d[4 * nt + 3] = i1;
            }
            int row0 = 16 * mt + gid;
            const int sw = 4 * gid;
#pragma unroll
            for (int kt = 0; kt < 4; ++kt) {
                int c0 = (8 * kt + tig) ^ sw;
                int c1 = (8 * kt + tig + 4) ^ sw;
                uint32_t a0 = *(const uint32_t*)(aT + row0 * 32 + c0);
                uint32_t a1 = *(const uint32_t*)(aT + (row0 + 8) * 32 + c0);
                uint32_t a2 = *(const uint32_t*)(aT + row0 * 32 + c1);
                uint32_t a3 = *(const uint32_t*)(aT + (row0 + 8) * 32 + c1);
#pragma unroll
                for (int nt = 0; nt < 4; ++nt) {
                    uint2 bp = sBfrag[kt][nt][lane];
                    mma_tf32(d + 4 * nt, a0, a1, a2, a3, bp.x, bp.y);
                }
            }
#pragma unroll
            for (int nt = 0; nt < 4; ++nt) {
                int colx = (8 * nt + 2 * tig) ^ sw;
                *(float2*)(hT + row0 * 32 + colx)       = make_float2(d[4 * nt + 0], d[4 * nt + 1]);
                *(float2*)(hT + (row0 + 8) * 32 + colx) = make_float2(d[4 * nt + 2], d[4 * nt + 3]);
            }
        }
        __syncwarp();

        // 3) epilogue: own row -> relu -> Wc2 -> sigmoid
        float A0 = bc2x, A1 = bc2y, A2 = bc2z;
#pragma unroll
        for (int g = 0; g < 8; ++g) {
            float4 h4 = *(const float4*)(hT + lane * 32 + 4 * (g ^ (lane & 7)));
            float h0 = fmaxf(h4.x, 0.0f), h1 = fmaxf(h4.y, 0.0f);
            float h2 = fmaxf(h4.z, 0.0f), h3 = fmaxf(h4.w, 0.0f);
            float4 u0 = *(const float4*)&sWc2c[0][4 * g];
            float4 u1 = *(const float4*)&sWc2c[1][4 * g];
            float4 u2 = *(const float4*)&sWc2c[2][4 * g];
            A0 = fmaf(h0, u0.x, A0); A1 = fmaf(h0, u1.x, A1); A2 = fmaf(h0, u2.x, A2);
            A0 = fmaf(h1, u0.y, A0); A1 = fmaf(h1, u1.y, A1); A2 = fmaf(h1, u2.y, A2);
            A0 = fmaf(h2, u0.z, A0); A1 = fmaf(h2, u1.z, A1); A2 = fmaf(h2, u2.z, A2);
            A0 = fmaf(h3, u0.w, A0); A1 = fmaf(h3, u1.w, A1); A2 = fmaf(h3, u2.w, A2);
        }
        rr[q] = fsigmoid(A0);
        rg[q] = fsigmoid(A1);
        rb[q] = fsigmoid(A2);
    }

    // ---- fine weights + accumulation ----
    float znx = __shfl_down_sync(0xffffffffu, zlf[0], 1);
    float dl[4];
    dl[0] = zlf[1] - zlf[0];
    dl[1] = zlf[2] - zlf[1];
    dl[2] = zlf[3] - zlf[2];
    dl[3] = (lane == 31) ? 0.0f : (znx - zlf[3]);

    float al[4], om2[4]; float lp = 1.0f;
#pragma unroll
    for (int q = 0; q < 4; ++q) {
        al[q] = 1.0f - fexp(-sig[q] * dl[q]);
        om2[q] = 1.0f - al[q];
        lp *= om2[q];
    }
    float scan2 = lp;
#pragma unroll
    for (int o = 1; o < 32; o <<= 1) {
        float t = __shfl_up_sync(0xffffffffu, scan2, o);
        if (lane >= o) scan2 *= t;
    }
    float T2 = __shfl_up_sync(0xffffffffu, scan2, 1);
    if (lane == 0) T2 = 1.0f;
    float w4[4];
#pragma unroll
    for (int q = 0; q < 4; ++q) { w4[q] = al[q] * T2; T2 *= om2[q]; }

    float ir = 0.0f, ig = 0.0f, ib = 0.0f, ivd = 0.0f, ws = 0.0f;
#pragma unroll
    for (int q = 0; q < 4; ++q) {
        ir = fmaf(w4[q], rr[q], ir);
        ig = fmaf(w4[q], rg[q], ig);
        ib = fmaf(w4[q], rb[q], ib);
        ivd = fmaf(w4[q], fexp10(-zlf[q]), ivd);
        ws  += w4[q];
    }
#pragma unroll
    for (int o = 16; o; o >>= 1) {
        ir  += __shfl_xor_sync(0xffffffffu, ir, o);
        ig  += __shfl_xor_sync(0xffffffffu, ig, o);
        ib  += __shfl_xor_sync(0xffffffffu, ib, o);
        ivd += __shfl_xor_sync(0xffffffffu, ivd, o);
        ws  += __shfl_xor_sync(0xffffffffu, ws, o);
    }

    // ---- stores ----
    *(float4*)(oW + (size_t)ray * NFINE + lane * 4) =
        make_float4(w4[0], w4[1], w4[2], w4[3]);
    *(float4*)(oZ + (size_t)ray * NFINE + lane * 4) =
        make_float4((zlf[0] + 1.0f) * 0.5f, (zlf[1] + 1.0f) * 0.5f,
                    (zlf[2] + 1.0f) * 0.5f, (zlf[3] + 1.0f) * 0.5f);

    if (lane == 0) {
        float oneMw = 1.0f - ws;
        oImg[ray * 3 + 0] = ir + oneMw * gbg[0];
        oImg[ray * 3 + 1] = ig + oneMw * gbg[1];
        oImg[ray * 3 + 2] = ib + oneMw * gbg[2];
        oInv[ray] = ivd;
    }
}

extern "C" void kernel_launch(void* const* d_in, const int* in_sizes, int n_in,
                              void* d_out, int out_size) {
    const float* h   = (const float*)d_in[1];
    const float* w   = (const float*)d_in[2];
    const float* K   = (const float*)d_in[3];
    const float* E   = (const float*)d_in[4];
    const float* bg  = (const float*)d_in[5];
    const float* Wd1 = (const float*)d_in[6];
    const float* bd1 = (const float*)d_in[7];
    const float* Wd2 = (const float*)d_in[8];
    const float* bd2 = (const float*)d_in[9];
    const float* Wc1 = (const float*)d_in[10];
    const float* bc1 = (const float*)d_in[11];
    const float* Wc2 = (const float*)d_in[12];
    const float* bc2 = (const float*)d_in[13];

    float* out   = (float*)d_out;
    float* oImg  = out;
    float* oW    = out + NRAYS * 3;
    float* oZ    = oW + (size_t)NRAYS * NFINE;
    float* oInv  = oZ + (size_t)NRAYS * NFINE;

    nerf_fused<<<NRAYS / 4, 128>>>(h, w, K, E, bg,
                                   Wd1, bd1, Wd2, bd2,
                                   Wc1, bc1, Wc2, bc2,
                                   oImg, oW, oZ, oInv);
}

// round 11
// speedup vs baseline: 2.0566x; 1.1335x over previous
#include <cuda_runtime.h>
#include <cstdint>

#define NRAYS 16384
#define NFINE 128

typedef unsigned long long u64;

// ---- fast transcendentals ----
__device__ __forceinline__ float fexp(float x)   { return __expf(x); }
__device__ __forceinline__ float fexp10(float x) { return __exp10f(x); }
__device__ __forceinline__ float frsqrt_approx(float x) {
    float r; asm("rsqrt.approx.f32 %0, %1;" : "=f"(r) : "f"(x)); return r;
}
__device__ __forceinline__ float fsigmoid(float x) {
    return __fdividef(1.0f, 1.0f + __expf(-x));
}
__device__ __forceinline__ float fsoftplus(float x) {
    return fmaxf(x, 0.0f) + __logf(1.0f + __expf(-fabsf(x)));
}
__device__ __forceinline__ uint32_t f2tf32(float x) {
    uint32_t r; asm("cvt.rna.tf32.f32 %0, %1;" : "=r"(r) : "f"(x)); return r;
}
// m16n8k8 tf32 HMMA (standard PTX, sm_80+; runs on sm_103 tensor pipe)
__device__ __forceinline__ void mma_tf32(float* d,
    uint32_t a0, uint32_t a1, uint32_t a2, uint32_t a3,
    uint32_t b0, uint32_t b1)
{
    asm volatile(
        "mma.sync.aligned.m16n8k8.row.col.f32.tf32.tf32.f32 "
        "{%0,%1,%2,%3}, {%4,%5,%6,%7}, {%8,%9}, {%0,%1,%2,%3};"
        : "+f"(d[0]), "+f"(d[1]), "+f"(d[2]), "+f"(d[3])
        : "r"(a0), "r"(a1), "r"(a2), "r"(a3), "r"(b0), "r"(b1));
}

// exact z-grid helpers
__device__ __forceinline__ float zlog_c(int i) {
    return (i < 128) ? (float)(i - 128) * 0.0078125f : (float)(i - 128) * 0.015625f;
}
__device__ __forceinline__ float zmid_c(int i) {
    return 0.5f * (zlog_c(i) + zlog_c(i + 1));
}
__device__ __forceinline__ unsigned rotl32(unsigned x, int r) {
    return __funnelshift_l(x, x, r);
}

// JAX threefry2x32, key=(0,42), partitionable counter mode: bits = out0^out1
__device__ __forceinline__ float tf_uniform(unsigned idx) {
    unsigned x0 = 0u, x1 = idx;
    const unsigned ks1 = 42u;
    const unsigned ks2 = 42u ^ 0x1BD11BDAu;
    x0 += 0u; x1 += ks1;
#define TF_RND(R) { x0 += x1; x1 = rotl32(x1, R); x1 ^= x0; }
    TF_RND(13) TF_RND(15) TF_RND(26) TF_RND(6)
    x0 += ks1; x1 += ks2 + 1u;
    TF_RND(17) TF_RND(29) TF_RND(16) TF_RND(24)
    x0 += ks2; x1 += 0u + 2u;
    TF_RND(13) TF_RND(15) TF_RND(26) TF_RND(6)
    x0 += 0u; x1 += ks1 + 3u;
    TF_RND(17) TF_RND(29) TF_RND(16) TF_RND(24)
    x0 += ks1; x1 += ks2 + 4u;
    TF_RND(13) TF_RND(15) TF_RND(26) TF_RND(6)
    x0 += ks2; x1 += 0u + 5u;
#undef TF_RND
    unsigned bits = x0 ^ x1;
    return __uint_as_float((bits >> 9) | 0x3f800000u) - 1.0f;
}

__device__ __forceinline__ void mip_scale(float& x, float& y, float& z) {
    float d2 = x * x + y * y + z * z;
    float r  = frsqrt_approx(d2);
    float d  = d2 * r;
    if (d > 1.0f) {
        float s = (2.0f - r) * r;
        x *= s; y *= s; z *= s;
    }
}

__global__ void __launch_bounds__(128, 4) nerf_fused(
    const float* __restrict__ gh, const float* __restrict__ gw,
    const float* __restrict__ gK, const float* __restrict__ gE,
    const float* __restrict__ gbg,
    const float* __restrict__ gWd1, const float* __restrict__ gbd1,
    const float* __restrict__ gWd2, const float* __restrict__ gbd2,
    const float* __restrict__ gWc1, const float* __restrict__ gbc1,
    const float* __restrict__ gWc2, const float* __restrict__ gbc2,
    float* __restrict__ oImg, float* __restrict__ oW,
    float* __restrict__ oZ, float* __restrict__ oInv)
{
    __shared__ float4 sWd1p[32];            // (w0,w1,w2,b) per hidden c
    __shared__ float  sWd2[32];
    __shared__ __align__(16) float sWc2c[3][32];
    __shared__ float  sInit[4][32];         // per-ray bc1 + dir terms
    __shared__ uint2  sBfrag[4][4][32];     // b-frags [kt][nt][lane] = (b0,b1) tf32
    __shared__ float  sCdf[4][256];
    __shared__ __align__(16) float sT[4][1024];  // per-warp T tile (also rgb exchange)

    const int tid  = threadIdx.x;
    const int lane = tid & 31;
    const int warp = tid >> 5;
    const int gid  = lane >> 2;
    const int tig  = lane & 3;
    const int ray  = (blockIdx.x << 2) + warp;

    // ---- stage weights + B fragments ----
    if (tid < 32) {
        sWd1p[tid] = make_float4(gWd1[tid], gWd1[32 + tid], gWd1[64 + tid], gbd1[tid]);
        sWd2[tid]  = gWd2[tid];
        sWc2c[0][tid] = gWc2[tid * 3 + 0];
        sWc2c[1][tid] = gWc2[tid * 3 + 1];
        sWc2c[2][tid] = gWc2[tid * 3 + 2];
    }
    for (int i = tid; i < 512; i += 128) {
        int kt = i >> 7, nt = (i >> 5) & 3, l = i & 31;
        int lt = l & 3, lg = l >> 2;
        int c0 = 8 * kt + lt, j = 8 * nt + lg;
        sBfrag[kt][nt][l] = make_uint2(f2tf32(gWc1[c0 * 32 + j]),
                                       f2tf32(gWc1[(c0 + 4) * 32 + j]));
    }
    __syncthreads();

    // ---- ray setup ----
    float k00 = gK[0], k01 = gK[1], k02 = gK[2];
    float k10 = gK[3], k11 = gK[4], k12 = gK[5];
    float k20 = gK[6], k21 = gK[7], k22 = gK[8];
    float det = k00 * (k11 * k22 - k12 * k21)
              + k01 * (k12 * k20 - k10 * k22)
              + k02 * (k10 * k21 - k11 * k20);
    float id = 1.0f / det;
    float i00 = (k11 * k22 - k12 * k21) * id, i01 = (k02 * k21 - k01 * k22) * id, i02 = (k01 * k12 - k02 * k11) * id;
    float i10 = (k12 * k20 - k10 * k22) * id, i11 = (k00 * k22 - k02 * k20) * id, i12 = (k02 * k10 - k00 * k12) * id;
    float i20 = (k10 * k21 - k11 * k20) * id, i21 = (k01 * k20 - k00 * k21) * id, i22 = (k00 * k11 - k01 * k10) * id;

    float dvx = gw[ray] + 0.5f, dvy = gh[ray] + 0.5f;
    float cx = dvx * i00 + dvy * i01 + i02;
    float cy = dvx * i10 + dvy * i11 + i12;
    float cz = dvx * i20 + dvy * i21 + i22;

    const float* Er = gE + (size_t)ray * 16;
    float ox = Er[3], oy = Er[7], oz = Er[11];
    float rdx = Er[0] * cx + Er[1] * cy + Er[2]  * cz;
    float rdy = Er[4] * cx + Er[5] * cy + Er[6]  * cz;
    float rdz = Er[8] * cx + Er[9] * cy + Er[10] * cz;
    float rn  = sqrtf(rdx * rdx + rdy * rdy + rdz * rdz);
    float irn = __fdividef(1.0f, rn);
    float ndx = rdx * irn, ndy = rdy * irn, ndz = rdz * irn;

    const float bd2v = gbd2[0];

    // per-ray layer1 init: bc1[j] + dir terms (rows 32..34 of Wc1); lane j
    {
        int j = lane;
        float ini = gbc1[j];
        ini = fmaf(ndx, gWc1[1024 + j], ini);
        ini = fmaf(ndy, gWc1[1056 + j], ini);
        ini = fmaf(ndz, gWc1[1088 + j], ini);
        sInit[warp][j] = ini;
    }
    __syncwarp();

    // ---- coarse pass: 6 samples/lane, single pass over density weights ----
    float alpha[6];
    {
        float cpx[6], cpy[6], cpz[6];
#pragma unroll
        for (int q = 0; q < 6; ++q) {
            float zq = fexp10(zlog_c(lane * 6 + q));
            cpx[q] = fmaf(rdx, zq, ox);
            cpy[q] = fmaf(rdy, zq, oy);
            cpz[q] = fmaf(rdz, zq, oz);
            mip_scale(cpx[q], cpy[q], cpz[q]);
        }
        float sg[6] = { bd2v, bd2v, bd2v, bd2v, bd2v, bd2v };
#pragma unroll 4
        for (int c = 0; c < 32; ++c) {
            float4 wd = sWd1p[c];
            float v2 = sWd2[c];
#pragma unroll
            for (int q = 0; q < 6; ++q) {
                float t = fmaf(cpx[q], wd.x, fmaf(cpy[q], wd.y, fmaf(cpz[q], wd.z, wd.w)));
                t = fmaxf(t, 0.0f);
                sg[q] = fmaf(t, v2, sg[q]);
            }
        }
#pragma unroll
        for (int q = 0; q < 6; ++q) {
            int s = lane * 6 + q;
            float d = (s < 128) ? 0.0078125f : ((s < 191) ? 0.015625f : 0.0f);
            alpha[q] = 1.0f - fexp(-fsoftplus(sg[q]) * d);
        }
    }

    // ---- transmittance weights (warp multiplicative scan) ----
    float om[6]; float lprod = 1.0f;
#pragma unroll
    for (int q = 0; q < 6; ++q) { om[q] = 1.0f - alpha[q]; lprod *= om[q]; }
    float scanp = lprod;
#pragma unroll
    for (int o = 1; o < 32; o <<= 1) {
        float t = __shfl_up_sync(0xffffffffu, scanp, o);
        if (lane >= o) scanp *= t;
    }
    float T = __shfl_up_sync(0xffffffffu, scanp, 1);
    if (lane == 0) T = 1.0f;
    float wgt[6];
#pragma unroll
    for (int q = 0; q < 6; ++q) { wgt[q] = alpha[q] * T; T *= om[q]; }

    // ---- reweight ----
    float wprev = __shfl_up_sync(0xffffffffu, wgt[5], 1);   if (lane == 0)  wprev = 0.0f;
    float wnext = __shfl_down_sync(0xffffffffu, wgt[0], 1); if (lane == 31) wnext = 0.0f;
    float wr[6]; float lsum = 0.0f;
#pragma unroll
    for (int q = 0; q < 6; ++q) {
        float wm = (q == 0) ? wprev : wgt[q - 1];
        float wp = (q == 5) ? wnext : wgt[q + 1];
        float v = 0.5f * (fmaxf(wm, wgt[q]) + fmaxf(wgt[q], wp)) + (float)(0.02 / 192.0);
        int s = lane * 6 + q;
        v *= (s < 128) ? (float)(128.0 / 192.0) : (float)(64.0 / 192.0);
        wr[q] = v; lsum += v;
    }
    float tot = lsum;
#pragma unroll
    for (int o = 16; o; o >>= 1) tot += __shfl_xor_sync(0xffffffffu, tot, o);
    float itot = __fdividef(1.0f, tot);

    float wn[6]; float ls2 = 0.0f;
#pragma unroll
    for (int q = 0; q < 6; ++q) { wn[q] = wr[q] * itot; ls2 += wn[q]; }
    float scs = ls2;
#pragma unroll
    for (int o = 1; o < 32; o <<= 1) {
        float t = __shfl_up_sync(0xffffffffu, scs, o);
        if (lane >= o) scs += t;
    }
    float base = __shfl_up_sync(0xffffffffu, scs, 1);
    if (lane == 0) base = 0.0f;
    float run = base;
#pragma unroll
    for (int q = 0; q < 6; ++q) { run += wn[q]; sCdf[warp][lane * 6 + q] = run; }
    sCdf[warp][192 + lane] = 1e30f;
    sCdf[warp][224 + lane] = 1e30f;
    __syncwarp();

    const float cdfl = sCdf[warp][1];
    const float cdfh = sCdf[warp][190];

    // ---- importance sampling: unconditional branchless bit-ladder ----
    float zlf[4];
#pragma unroll
    for (int q = 0; q < 4; ++q) {
        int j = (lane << 2) + q;
        float r = tf_uniform((unsigned)(ray * NFINE + j));
        float u = (float)j * 0.0078125f + r * 0.0078125f;
        u = u * (cdfh - cdfl) + cdfl;
        int k = 0;
#pragma unroll
        for (int s = 128; s >= 1; s >>= 1) {
            int cand = k + s;
            if (sCdf[warp][cand] <= u) k = cand;
        }
        float cb = sCdf[warp][k], ca = sCdf[warp][k + 1];
        float tt = __fdividef(u - cb, ca - cb);
        float zb = zmid_c(k), za = zmid_c(k + 1);
        zlf[q] = zb + (za - zb) * tt;
    }

    // ---- fine pass: per q-tile (samples s = 4*lane + q), HMMA GEMM ----
    const float bc2x = gbc2[0], bc2y = gbc2[1], bc2z = gbc2[2];
    float* aT = sT[warp];
    float sig[4], rr[4], rg[4], rb[4];

#pragma unroll
    for (int q = 0; q < 4; ++q) {
        // 1) compute hidden t for own sample; stage tf32 T tile; sigma path fp32
        float zq = fexp10(zlf[q]);
        float pxq = fmaf(rdx, zq, ox), pyq = fmaf(rdy, zq, oy), pzq = fmaf(rdz, zq, oz);
        mip_scale(pxq, pyq, pzq);
        float sgq = bd2v;
#pragma unroll
        for (int cg = 0; cg < 8; ++cg) {
            uint4 tc;
#pragma unroll
            for (int cc = 0; cc < 4; ++cc) {
                int c = 4 * cg + cc;
                float4 wd = sWd1p[c];
                float t = fmaf(pxq, wd.x, fmaf(pyq, wd.y, fmaf(pzq, wd.z, wd.w)));
                t = fmaxf(t, 0.0f);
                sgq = fmaf(t, sWd2[c], sgq);
                ((uint32_t*)&tc)[cc] = f2tf32(t);
            }
            *(uint4*)(aT + lane * 32 + 4 * (cg ^ (lane & 7))) = tc;
        }
        sig[q] = fsoftplus(sgq);
        __syncwarp();

        // 2) GEMM + d-frag epilogue: rgb partials, no H materialization
        float part[4][3];
#pragma unroll
        for (int s = 0; s < 4; ++s) { part[s][0] = 0.0f; part[s][1] = 0.0f; part[s][2] = 0.0f; }

#pragma unroll
        for (int mt = 0; mt < 2; ++mt) {
            float d[16];
#pragma unroll
            for (int nt = 0; nt < 4; ++nt) {
                int j0 = 8 * nt + 2 * tig;
                float i0 = sInit[warp][j0], i1 = sInit[warp][j0 + 1];
                d[4 * nt + 0] = i0; d[4 * nt + 1] = i1;
                d[4 * nt + 2] = i0; d[4 * nt + 3] = i1;
            }
            int row0 = 16 * mt + gid;
            const int sw = 4 * gid;
#pragma unroll
            for (int kt = 0; kt < 4; ++kt) {
                int c0 = (8 * kt + tig) ^ sw;
                int c1 = (8 * kt + tig + 4) ^ sw;
                uint32_t a0 = *(const uint32_t*)(aT + row0 * 32 + c0);
                uint32_t a1 = *(const uint32_t*)(aT + (row0 + 8) * 32 + c0);
                uint32_t a2 = *(const uint32_t*)(aT + row0 * 32 + c1);
                uint32_t a3 = *(const uint32_t*)(aT + (row0 + 8) * 32 + c1);
#pragma unroll
                for (int nt = 0; nt < 4; ++nt) {
                    uint2 bp = sBfrag[kt][nt][lane];
                    mma_tf32(d + 4 * nt, a0, a1, a2, a3, bp.x, bp.y);
                }
            }
            // epilogue on d-frags: relu + Wc2 partial dot (cols 8nt+2tig, +1)
#pragma unroll
            for (int nt = 0; nt < 4; ++nt) {
                float h00 = fmaxf(d[4 * nt + 0], 0.0f);
                float h01 = fmaxf(d[4 * nt + 1], 0.0f);
                float h10 = fmaxf(d[4 * nt + 2], 0.0f);
                float h11 = fmaxf(d[4 * nt + 3], 0.0f);
                int jj = 8 * nt + 2 * tig;
#pragma unroll
                for (int c = 0; c < 3; ++c) {
                    float2 u2 = *(const float2*)&sWc2c[c][jj];
                    part[2 * mt + 0][c] = fmaf(h00, u2.x, fmaf(h01, u2.y, part[2 * mt + 0][c]));
                    part[2 * mt + 1][c] = fmaf(h10, u2.x, fmaf(h11, u2.y, part[2 * mt + 1][c]));
                }
            }
        }

        // 3) tig-group butterfly reduction (cols 8nt+2tig cover all 32 over tig)
#pragma unroll
        for (int s = 0; s < 4; ++s)
#pragma unroll
            for (int c = 0; c < 3; ++c) {
                part[s][c] += __shfl_xor_sync(0xffffffffu, part[s][c], 1);
                part[s][c] += __shfl_xor_sync(0xffffffffu, part[s][c], 2);
            }

        // 4) exchange to sample-owner lane via SMEM (reuse T buffer; T is dead)
        __syncwarp();
        float4* exch = (float4*)aT;
        if (tig == 0) {
#pragma unroll
            for (int s = 0; s < 4; ++s) {
                int row = 16 * (s >> 1) + 8 * (s & 1) + gid;
                exch[row] = make_float4(part[s][0], part[s][1], part[s][2], 0.0f);
            }
        }
        __syncwarp();
        float4 v = exch[lane];
        rr[q] = fsigmoid(v.x + bc2x);
        rg[q] = fsigmoid(v.y + bc2y);
        rb[q] = fsigmoid(v.z + bc2z);
        __syncwarp();
    }

    // ---- fine weights + accumulation ----
    float znx = __shfl_down_sync(0xffffffffu, zlf[0], 1);
    float dl[4];
    dl[0] = zlf[1] - zlf[0];
    dl[1] = zlf[2] - zlf[1];
    dl[2] = zlf[3] - zlf[2];
    dl[3] = (lane == 31) ? 0.0f : (znx - zlf[3]);

    float al[4], om2[4]; float lp = 1.0f;
#pragma unroll
    for (int q = 0; q < 4; ++q) {
        al[q] = 1.0f - fexp(-sig[q] * dl[q]);
        om2[q] = 1.0f - al[q];
        lp *= om2[q];
    }
    float scan2 = lp;
#pragma unroll
    for (int o = 1; o < 32; o <<= 1) {
        float t = __shfl_up_sync(0xffffffffu, scan2, o);
        if (lane >= o) scan2 *= t;
    }
    float T2 = __shfl_up_sync(0xffffffffu, scan2, 1);
    if (lane == 0) T2 = 1.0f;
    float w4[4];
#pragma unroll
    for (int q = 0; q < 4; ++q) { w4[q] = al[q] * T2; T2 *= om2[q]; }

    float ir = 0.0f, ig = 0.0f, ib = 0.0f, ivd = 0.0f, ws = 0.0f;
#pragma unroll
    for (int q = 0; q < 4; ++q) {
        ir = fmaf(w4[q], rr[q], ir);
        ig = fmaf(w4[q], rg[q], ig);
        ib = fmaf(w4[q], rb[q], ib);
        ivd = fmaf(w4[q], fexp10(-zlf[q]), ivd);
        ws  += w4[q];
    }
#pragma unroll
    for (int o = 16; o; o >>= 1) {
        ir  += __shfl_xor_sync(0xffffffffu, ir, o);
        ig  += __shfl_xor_sync(0xffffffffu, ig, o);
        ib  += __shfl_xor_sync(0xffffffffu, ib, o);
        ivd += __shfl_xor_sync(0xffffffffu, ivd, o);
        ws  += __shfl_xor_sync(0xffffffffu, ws, o);
    }

    // ---- stores ----
    *(float4*)(oW + (size_t)ray * NFINE + lane * 4) =
        make_float4(w4[0], w4[1], w4[2], w4[3]);
    *(float4*)(oZ + (size_t)ray * NFINE + lane * 4) =
        make_float4((zlf[0] + 1.0f) * 0.5f, (zlf[1] + 1.0f) * 0.5f,
                    (zlf[2] + 1.0f) * 0.5f, (zlf[3] + 1.0f) * 0.5f);

    if (lane == 0) {
        float oneMw = 1.0f - ws;
        oImg[ray * 3 + 0] = ir + oneMw * gbg[0];
        oImg[ray * 3 + 1] = ig + oneMw * gbg[1];
        oImg[ray * 3 + 2] = ib + oneMw * gbg[2];
        oInv[ray] = ivd;
    }
}

extern "C" void kernel_launch(void* const* d_in, const int* in_sizes, int n_in,
                              void* d_out, int out_size) {
    const float* h   = (const float*)d_in[1];
    const float* w   = (const float*)d_in[2];
    const float* K   = (const float*)d_in[3];
    const float* E   = (const float*)d_in[4];
    const float* bg  = (const float*)d_in[5];
    const float* Wd1 = (const float*)d_in[6];
    const float* bd1 = (const float*)d_in[7];
    const float* Wd2 = (const float*)d_in[8];
    const float* bd2 = (const float*)d_in[9];
    const float* Wc1 = (const float*)d_in[10];
    const float* bc1 = (const float*)d_in[11];
    const float* Wc2 = (const float*)d_in[12];
    const float* bc2 = (const float*)d_in[13];

    float* out   = (float*)d_out;
    float* oImg  = out;
    float* oW    = out + NRAYS * 3;
    float* oZ    = oW + (size_t)NRAYS * NFINE;
    float* oInv  = oZ + (size_t)NRAYS * NFINE;

    nerf_fused<<<NRAYS / 4, 128>>>(h, w, K, E, bg,
                                   Wd1, bd1, Wd2, bd2,
                                   Wc1, bc1, Wc2, bc2,
                                   oImg, oW, oZ, oInv);
}

// round 12
// speedup vs baseline: 2.0730x; 1.0080x over previous
#include <cuda_runtime.h>
#include <cstdint>

#define NRAYS 16384
#define NFINE 128

typedef unsigned long long u64;

// ---- fast transcendentals ----
__device__ __forceinline__ float fexp(float x)   { return __expf(x); }
__device__ __forceinline__ float fexp10(float x) { return __exp10f(x); }
__device__ __forceinline__ float frsqrt_approx(float x) {
    float r; asm("rsqrt.approx.f32 %0, %1;" : "=f"(r) : "f"(x)); return r;
}
__device__ __forceinline__ float fsigmoid(float x) {
    return __fdividef(1.0f, 1.0f + __expf(-x));
}
__device__ __forceinline__ float fsoftplus(float x) {
    return fmaxf(x, 0.0f) + __logf(1.0f + __expf(-fabsf(x)));
}
__device__ __forceinline__ uint32_t f2tf32(float x) {
    uint32_t r; asm("cvt.rna.tf32.f32 %0, %1;" : "=r"(r) : "f"(x)); return r;
}
// m16n8k8 tf32 HMMA (standard PTX, sm_80+; runs on sm_103 tensor pipe)
__device__ __forceinline__ void mma_tf32(float* d,
    uint32_t a0, uint32_t a1, uint32_t a2, uint32_t a3,
    uint32_t b0, uint32_t b1)
{
    asm volatile(
        "mma.sync.aligned.m16n8k8.row.col.f32.tf32.tf32.f32 "
        "{%0,%1,%2,%3}, {%4,%5,%6,%7}, {%8,%9}, {%0,%1,%2,%3};"
        : "+f"(d[0]), "+f"(d[1]), "+f"(d[2]), "+f"(d[3])
        : "r"(a0), "r"(a1), "r"(a2), "r"(a3), "r"(b0), "r"(b1));
}

// exact z-grid helpers
__device__ __forceinline__ float zlog_c(int i) {
    return (i < 128) ? (float)(i - 128) * 0.0078125f : (float)(i - 128) * 0.015625f;
}
__device__ __forceinline__ float zmid_c(int i) {
    return 0.5f * (zlog_c(i) + zlog_c(i + 1));
}
__device__ __forceinline__ unsigned rotl32(unsigned x, int r) {
    return __funnelshift_l(x, x, r);
}

// JAX threefry2x32, key=(0,42), partitionable counter mode: bits = out0^out1
__device__ __forceinline__ float tf_uniform(unsigned idx) {
    unsigned x0 = 0u, x1 = idx;
    const unsigned ks1 = 42u;
    const unsigned ks2 = 42u ^ 0x1BD11BDAu;
    x0 += 0u; x1 += ks1;
#define TF_RND(R) { x0 += x1; x1 = rotl32(x1, R); x1 ^= x0; }
    TF_RND(13) TF_RND(15) TF_RND(26) TF_RND(6)
    x0 += ks1; x1 += ks2 + 1u;
    TF_RND(17) TF_RND(29) TF_RND(16) TF_RND(24)
    x0 += ks2; x1 += 0u + 2u;
    TF_RND(13) TF_RND(15) TF_RND(26) TF_RND(6)
    x0 += 0u; x1 += ks1 + 3u;
    TF_RND(17) TF_RND(29) TF_RND(16) TF_RND(24)
    x0 += ks1; x1 += ks2 + 4u;
    TF_RND(13) TF_RND(15) TF_RND(26) TF_RND(6)
    x0 += ks2; x1 += 0u + 5u;
#undef TF_RND
    unsigned bits = x0 ^ x1;
    return __uint_as_float((bits >> 9) | 0x3f800000u) - 1.0f;
}

__device__ __forceinline__ void mip_scale(float& x, float& y, float& z) {
    float d2 = x * x + y * y + z * z;
    float r  = frsqrt_approx(d2);
    float d  = d2 * r;
    if (d > 1.0f) {
        float s = (2.0f - r) * r;
        x *= s; y *= s; z *= s;
    }
}

__global__ void __launch_bounds__(128, 4) nerf_fused(
    const float* __restrict__ gh, const float* __restrict__ gw,
    const float* __restrict__ gK, const float* __restrict__ gE,
    const float* __restrict__ gbg,
    const float* __restrict__ gWd1, const float* __restrict__ gbd1,
    const float* __restrict__ gWd2, const float* __restrict__ gbd2,
    const float* __restrict__ gWc1, const float* __restrict__ gbc1,
    const float* __restrict__ gWc2, const float* __restrict__ gbc2,
    float* __restrict__ oImg, float* __restrict__ oW,
    float* __restrict__ oZ, float* __restrict__ oInv)
{
    __shared__ float4 sWd1p[32];            // (w0,w1,w2,b) per hidden c
    __shared__ float  sWd2[32];
    __shared__ __align__(16) float sWc2c[3][32];
    __shared__ float  sInit[4][32];         // per-ray bc1 + dir terms
    __shared__ uint2  sBfrag[4][4][32];     // b-frags [kt][nt][lane] = (b0,b1) tf32
    __shared__ float  sCdf[4][256];
    __shared__ __align__(16) float sT[4][1024];  // per-warp T tile (also rgb exchange)

    const int tid  = threadIdx.x;
    const int lane = tid & 31;
    const int warp = tid >> 5;
    const int gid  = lane >> 2;
    const int tig  = lane & 3;
    const int ray  = (blockIdx.x << 2) + warp;

    // ---- stage weights + B fragments ----
    if (tid < 32) {
        sWd1p[tid] = make_float4(gWd1[tid], gWd1[32 + tid], gWd1[64 + tid], gbd1[tid]);
        sWd2[tid]  = gWd2[tid];
        sWc2c[0][tid] = gWc2[tid * 3 + 0];
        sWc2c[1][tid] = gWc2[tid * 3 + 1];
        sWc2c[2][tid] = gWc2[tid * 3 + 2];
    }
    for (int i = tid; i < 512; i += 128) {
        int kt = i >> 7, nt = (i >> 5) & 3, l = i & 31;
        int lt = l & 3, lg = l >> 2;
        int c0 = 8 * kt + lt, j = 8 * nt + lg;
        sBfrag[kt][nt][l] = make_uint2(f2tf32(gWc1[c0 * 32 + j]),
                                       f2tf32(gWc1[(c0 + 4) * 32 + j]));
    }
    __syncthreads();

    // ---- ray setup ----
    float k00 = gK[0], k01 = gK[1], k02 = gK[2];
    float k10 = gK[3], k11 = gK[4], k12 = gK[5];
    float k20 = gK[6], k21 = gK[7], k22 = gK[8];
    float det = k00 * (k11 * k22 - k12 * k21)
              + k01 * (k12 * k20 - k10 * k22)
              + k02 * (k10 * k21 - k11 * k20);
    float id = 1.0f / det;
    float i00 = (k11 * k22 - k12 * k21) * id, i01 = (k02 * k21 - k01 * k22) * id, i02 = (k01 * k12 - k02 * k11) * id;
    float i10 = (k12 * k20 - k10 * k22) * id, i11 = (k00 * k22 - k02 * k20) * id, i12 = (k02 * k10 - k00 * k12) * id;
    float i20 = (k10 * k21 - k11 * k20) * id, i21 = (k01 * k20 - k00 * k21) * id, i22 = (k00 * k11 - k01 * k10) * id;

    float dvx = gw[ray] + 0.5f, dvy = gh[ray] + 0.5f;
    float cx = dvx * i00 + dvy * i01 + i02;
    float cy = dvx * i10 + dvy * i11 + i12;
    float cz = dvx * i20 + dvy * i21 + i22;

    const float* Er = gE + (size_t)ray * 16;
    float ox = Er[3], oy = Er[7], oz = Er[11];
    float rdx = Er[0] * cx + Er[1] * cy + Er[2]  * cz;
    float rdy = Er[4] * cx + Er[5] * cy + Er[6]  * cz;
    float rdz = Er[8] * cx + Er[9] * cy + Er[10] * cz;
    float rn  = sqrtf(rdx * rdx + rdy * rdy + rdz * rdz);
    float irn = __fdividef(1.0f, rn);
    float ndx = rdx * irn, ndy = rdy * irn, ndz = rdz * irn;

    const float bd2v = gbd2[0];

    // per-ray layer1 init: bc1[j] + dir terms (rows 32..34 of Wc1); lane j
    {
        int j = lane;
        float ini = gbc1[j];
        ini = fmaf(ndx, gWc1[1024 + j], ini);
        ini = fmaf(ndy, gWc1[1056 + j], ini);
        ini = fmaf(ndz, gWc1[1088 + j], ini);
        sInit[warp][j] = ini;
    }
    __syncwarp();

    // ---- coarse pass: 6 samples/lane, single pass over density weights ----
    float alpha[6];
    {
        float cpx[6], cpy[6], cpz[6];
#pragma unroll
        for (int q = 0; q < 6; ++q) {
            float zq = fexp10(zlog_c(lane * 6 + q));
            cpx[q] = fmaf(rdx, zq, ox);
            cpy[q] = fmaf(rdy, zq, oy);
            cpz[q] = fmaf(rdz, zq, oz);
            mip_scale(cpx[q], cpy[q], cpz[q]);
        }
        float sg[6] = { bd2v, bd2v, bd2v, bd2v, bd2v, bd2v };
#pragma unroll 4
        for (int c = 0; c < 32; ++c) {
            float4 wd = sWd1p[c];
            float v2 = sWd2[c];
#pragma unroll
            for (int q = 0; q < 6; ++q) {
                float t = fmaf(cpx[q], wd.x, fmaf(cpy[q], wd.y, fmaf(cpz[q], wd.z, wd.w)));
                t = fmaxf(t, 0.0f);
                sg[q] = fmaf(t, v2, sg[q]);
            }
        }
#pragma unroll
        for (int q = 0; q < 6; ++q) {
            int s = lane * 6 + q;
            float d = (s < 128) ? 0.0078125f : ((s < 191) ? 0.015625f : 0.0f);
            alpha[q] = 1.0f - fexp(-fsoftplus(sg[q]) * d);
        }
    }

    // ---- transmittance weights (warp multiplicative scan) ----
    float om[6]; float lprod = 1.0f;
#pragma unroll
    for (int q = 0; q < 6; ++q) { om[q] = 1.0f - alpha[q]; lprod *= om[q]; }
    float scanp = lprod;
#pragma unroll
    for (int o = 1; o < 32; o <<= 1) {
        float t = __shfl_up_sync(0xffffffffu, scanp, o);
        if (lane >= o) scanp *= t;
    }
    float T = __shfl_up_sync(0xffffffffu, scanp, 1);
    if (lane == 0) T = 1.0f;
    float wgt[6];
#pragma unroll
    for (int q = 0; q < 6; ++q) { wgt[q] = alpha[q] * T; T *= om[q]; }

    // ---- reweight ----
    float wprev = __shfl_up_sync(0xffffffffu, wgt[5], 1);   if (lane == 0)  wprev = 0.0f;
    float wnext = __shfl_down_sync(0xffffffffu, wgt[0], 1); if (lane == 31) wnext = 0.0f;
    float wr[6]; float lsum = 0.0f;
#pragma unroll
    for (int q = 0; q < 6; ++q) {
        float wm = (q == 0) ? wprev : wgt[q - 1];
        float wp = (q == 5) ? wnext : wgt[q + 1];
        float v = 0.5f * (fmaxf(wm, wgt[q]) + fmaxf(wgt[q], wp)) + (float)(0.02 / 192.0);
        int s = lane * 6 + q;
        v *= (s < 128) ? (float)(128.0 / 192.0) : (float)(64.0 / 192.0);
        wr[q] = v; lsum += v;
    }
    float tot = lsum;
#pragma unroll
    for (int o = 16; o; o >>= 1) tot += __shfl_xor_sync(0xffffffffu, tot, o);
    float itot = __fdividef(1.0f, tot);

    float wn[6]; float ls2 = 0.0f;
#pragma unroll
    for (int q = 0; q < 6; ++q) { wn[q] = wr[q] * itot; ls2 += wn[q]; }
    float scs = ls2;
#pragma unroll
    for (int o = 1; o < 32; o <<= 1) {
        float t = __shfl_up_sync(0xffffffffu, scs, o);
        if (lane >= o) scs += t;
    }
    float base = __shfl_up_sync(0xffffffffu, scs, 1);
    if (lane == 0) base = 0.0f;
    float run = base;
#pragma unroll
    for (int q = 0; q < 6; ++q) { run += wn[q]; sCdf[warp][lane * 6 + q] = run; }
    sCdf[warp][192 + lane] = 1e30f;
    sCdf[warp][224 + lane] = 1e30f;
    __syncwarp();

    const float cdfl = sCdf[warp][1];
    const float cdfh = sCdf[warp][190];

    // ---- importance sampling: unconditional branchless bit-ladder ----
    float zlf[4];
#pragma unroll
    for (int q = 0; q < 4; ++q) {
        int j = (lane << 2) + q;
        float r = tf_uniform((unsigned)(ray * NFINE + j));
        float u = (float)j * 0.0078125f + r * 0.0078125f;
        u = u * (cdfh - cdfl) + cdfl;
        int k = 0;
#pragma unroll
        for (int s = 128; s >= 1; s >>= 1) {
            int cand = k + s;
            if (sCdf[warp][cand] <= u) k = cand;
        }
        float cb = sCdf[warp][k], ca = sCdf[warp][k + 1];
        float tt = __fdividef(u - cb, ca - cb);
        float zb = zmid_c(k), za = zmid_c(k + 1);
        zlf[q] = zb + (za - zb) * tt;
    }

    // ---- fine pass: per q-tile (samples s = 4*lane + q), HMMA GEMM ----
    const float bc2x = gbc2[0], bc2y = gbc2[1], bc2z = gbc2[2];
    float* aT = sT[warp];
    float sig[4], rr[4], rg[4], rb[4];

    // q-invariant init pairs (cols 8nt+2tig, +1), hoisted out of q-loop
    float2 iniv[4];
#pragma unroll
    for (int nt = 0; nt < 4; ++nt)
        iniv[nt] = *(const float2*)&sInit[warp][8 * nt + 2 * tig];

#pragma unroll
    for (int q = 0; q < 4; ++q) {
        // 1) compute hidden t for own sample; stage tf32 T tile; sigma path fp32
        float zq = fexp10(zlf[q]);
        float pxq = fmaf(rdx, zq, ox), pyq = fmaf(rdy, zq, oy), pzq = fmaf(rdz, zq, oz);
        mip_scale(pxq, pyq, pzq);
        float sgq = bd2v;
#pragma unroll
        for (int cg = 0; cg < 8; ++cg) {
            uint4 tc;
#pragma unroll
            for (int cc = 0; cc < 4; ++cc) {
                int c = 4 * cg + cc;
                float4 wd = sWd1p[c];
                float t = fmaf(pxq, wd.x, fmaf(pyq, wd.y, fmaf(pzq, wd.z, wd.w)));
                t = fmaxf(t, 0.0f);
                sgq = fmaf(t, sWd2[c], sgq);
                ((uint32_t*)&tc)[cc] = f2tf32(t);
            }
            *(uint4*)(aT + lane * 32 + 4 * (cg ^ (lane & 7))) = tc;
        }
        sig[q] = fsoftplus(sgq);
        __syncwarp();

        // 2) GEMM, kt-outer with both m-tiles live (b-frags loaded ONCE per q)
        float d[32];                 // [mt][nt][4]
#pragma unroll
        for (int mt = 0; mt < 2; ++mt)
#pragma unroll
            for (int nt = 0; nt < 4; ++nt) {
                d[16 * mt + 4 * nt + 0] = iniv[nt].x;
                d[16 * mt + 4 * nt + 1] = iniv[nt].y;
                d[16 * mt + 4 * nt + 2] = iniv[nt].x;
                d[16 * mt + 4 * nt + 3] = iniv[nt].y;
            }
        const int sw = 4 * gid;
#pragma unroll
        for (int kt = 0; kt < 4; ++kt) {
            int c0 = (8 * kt + tig) ^ sw;
            int c1 = (8 * kt + tig + 4) ^ sw;
            uint32_t a0 = *(const uint32_t*)(aT + gid * 32 + c0);
            uint32_t a1 = *(const uint32_t*)(aT + (gid + 8) * 32 + c0);
            uint32_t a2 = *(const uint32_t*)(aT + gid * 32 + c1);
            uint32_t a3 = *(const uint32_t*)(aT + (gid + 8) * 32 + c1);
            uint32_t a4 = *(const uint32_t*)(aT + (gid + 16) * 32 + c0);
            uint32_t a5 = *(const uint32_t*)(aT + (gid + 24) * 32 + c0);
            uint32_t a6 = *(const uint32_t*)(aT + (gid + 16) * 32 + c1);
            uint32_t a7 = *(const uint32_t*)(aT + (gid + 24) * 32 + c1);
#pragma unroll
            for (int nt = 0; nt < 4; ++nt) {
                uint2 bp = sBfrag[kt][nt][lane];
                mma_tf32(d + 4 * nt,      a0, a1, a2, a3, bp.x, bp.y);
                mma_tf32(d + 16 + 4 * nt, a4, a5, a6, a7, bp.x, bp.y);
            }
        }

        // 3) d-frag epilogue: relu + Wc2 partial dot (cols 8nt+2tig, +1)
        float part[4][3];
#pragma unroll
        for (int s = 0; s < 4; ++s) { part[s][0] = 0.0f; part[s][1] = 0.0f; part[s][2] = 0.0f; }
#pragma unroll
        for (int mt = 0; mt < 2; ++mt)
#pragma unroll
            for (int nt = 0; nt < 4; ++nt) {
                float h00 = fmaxf(d[16 * mt + 4 * nt + 0], 0.0f);
                float h01 = fmaxf(d[16 * mt + 4 * nt + 1], 0.0f);
                float h10 = fmaxf(d[16 * mt + 4 * nt + 2], 0.0f);
                float h11 = fmaxf(d[16 * mt + 4 * nt + 3], 0.0f);
                int jj = 8 * nt + 2 * tig;
#pragma unroll
                for (int c = 0; c < 3; ++c) {
                    float2 u2 = *(const float2*)&sWc2c[c][jj];
                    part[2 * mt + 0][c] = fmaf(h00, u2.x, fmaf(h01, u2.y, part[2 * mt + 0][c]));
                    part[2 * mt + 1][c] = fmaf(h10, u2.x, fmaf(h11, u2.y, part[2 * mt + 1][c]));
                }
            }

        // 4) tig-group butterfly reduction (cols 8nt+2tig cover all 32 over tig)
#pragma unroll
        for (int s = 0; s < 4; ++s)
#pragma unroll
            for (int c = 0; c < 3; ++c) {
                part[s][c] += __shfl_xor_sync(0xffffffffu, part[s][c], 1);
                part[s][c] += __shfl_xor_sync(0xffffffffu, part[s][c], 2);
            }

        // 5) exchange to sample-owner lane via SMEM (reuse T buffer; T is dead)
        __syncwarp();
        float4* exch = (float4*)aT;
        if (tig == 0) {
#pragma unroll
            for (int s = 0; s < 4; ++s) {
                int row = 16 * (s >> 1) + 8 * (s & 1) + gid;
                exch[row] = make_float4(part[s][0], part[s][1], part[s][2], 0.0f);
            }
        }
        __syncwarp();
        float4 v = exch[lane];
        rr[q] = fsigmoid(v.x + bc2x);
        rg[q] = fsigmoid(v.y + bc2y);
        rb[q] = fsigmoid(v.z + bc2z);
        __syncwarp();
    }

    // ---- fine weights + accumulation ----
    float znx = __shfl_down_sync(0xffffffffu, zlf[0], 1);
    float dl[4];
    dl[0] = zlf[1] - zlf[0];
    dl[1] = zlf[2] - zlf[1];
    dl[2] = zlf[3] - zlf[2];
    dl[3] = (lane == 31) ? 0.0f : (znx - zlf[3]);

    float al[4], om2[4]; float lp = 1.0f;
#pragma unroll
    for (int q = 0; q < 4; ++q) {
        al[q] = 1.0f - fexp(-sig[q] * dl[q]);
        om2[q] = 1.0f - al[q];
        lp *= om2[q];
    }
    float scan2 = lp;
#pragma unroll
    for (int o = 1; o < 32; o <<= 1) {
        float t = __shfl_up_sync(0xffffffffu, scan2, o);
        if (lane >= o) scan2 *= t;
    }
    float T2 = __shfl_up_sync(0xffffffffu, scan2, 1);
    if (lane == 0) T2 = 1.0f;
    float w4[4];
#pragma unroll
    for (int q = 0; q < 4; ++q) { w4[q] = al[q] * T2; T2 *= om2[q]; }

    float ir = 0.0f, ig = 0.0f, ib = 0.0f, ivd = 0.0f, ws = 0.0f;
#pragma unroll
    for (int q = 0; q < 4; ++q) {
        ir = fmaf(w4[q], rr[q], ir);
        ig = fmaf(w4[q], rg[q], ig);
        ib = fmaf(w4[q], rb[q], ib);
        ivd = fmaf(w4[q], fexp10(-zlf[q]), ivd);
        ws  += w4[q];
    }
#pragma unroll
    for (int o = 16; o; o >>= 1) {
        ir  += __shfl_xor_sync(0xffffffffu, ir, o);
        ig  += __shfl_xor_sync(0xffffffffu, ig, o);
        ib  += __shfl_xor_sync(0xffffffffu, ib, o);
        ivd += __shfl_xor_sync(0xffffffffu, ivd, o);
        ws  += __shfl_xor_sync(0xffffffffu, ws, o);
    }

    // ---- stores ----
    *(float4*)(oW + (size_t)ray * NFINE + lane * 4) =
        make_float4(w4[0], w4[1], w4[2], w4[3]);
    *(float4*)(oZ + (size_t)ray * NFINE + lane * 4) =
        make_float4((zlf[0] + 1.0f) * 0.5f, (zlf[1] + 1.0f) * 0.5f,
                    (zlf[2] + 1.0f) * 0.5f, (zlf[3] + 1.0f) * 0.5f);

    if (lane == 0) {
        float oneMw = 1.0f - ws;
        oImg[ray * 3 + 0] = ir + oneMw * gbg[0];
        oImg[ray * 3 + 1] = ig + oneMw * gbg[1];
        oImg[ray * 3 + 2] = ib + oneMw * gbg[2];
        oInv[ray] = ivd;
    }
}

extern "C" void kernel_launch(void* const* d_in, const int* in_sizes, int n_in,
                              void* d_out, int out_size) {
    const float* h   = (const float*)d_in[1];
    const float* w   = (const float*)d_in[2];
    const float* K   = (const float*)d_in[3];
    const float* E   = (const float*)d_in[4];
    const float* bg  = (const float*)d_in[5];
    const float* Wd1 = (const float*)d_in[6];
    const float* bd1 = (const float*)d_in[7];
    const float* Wd2 = (const float*)d_in[8];
    const float* bd2 = (const float*)d_in[9];
    const float* Wc1 = (const float*)d_in[10];
    const float* bc1 = (const float*)d_in[11];
    const float* Wc2 = (const float*)d_in[12];
    const float* bc2 = (const float*)d_in[13];

    float* out   = (float*)d_out;
    float* oImg  = out;
    float* oW    = out + NRAYS * 3;
    float* oZ    = oW + (size_t)NRAYS * NFINE;
    float* oInv  = oZ + (size_t)NRAYS * NFINE;

    nerf_fused<<<NRAYS / 4, 128>>>(h, w, K, E, bg,
                                   Wd1, bd1, Wd2, bd2,
                                   Wc1, bc1, Wc2, bc2,
                                   oImg, oW, oZ, oInv);
}